// round 9
// baseline (speedup 1.0000x reference)
#include <cuda_runtime.h>
#include <cuda_bf16.h>
#include <math.h>
#include <stdint.h>

#define T_SEQ 4096
#define C_EMB 768
#define NH    12
#define HD    64
#define NW4   147456          // (768*768)/4
#define NX4   786432          // (4096*768)/4

typedef __nv_bfloat16 bf16;
typedef __nv_bfloat162 bf162;

// ---------------------------------------------------------------------------
// Scratch (__device__ globals — allocation-guard-safe)
// ---------------------------------------------------------------------------
__device__ __align__(128) bf16 g_xhi[(size_t)T_SEQ * C_EMB];
__device__ __align__(128) bf16 g_xlo[(size_t)T_SEQ * C_EMB];
__device__ __align__(128) bf16 g_whi[4][(size_t)C_EMB * C_EMB];
__device__ __align__(128) bf16 g_wlo[4][(size_t)C_EMB * C_EMB];
__device__ __align__(128) bf16 g_qhi[(size_t)NH * T_SEQ * HD];
__device__ __align__(128) bf16 g_qlo[(size_t)NH * T_SEQ * HD];
__device__ __align__(128) bf16 g_khi[(size_t)NH * T_SEQ * HD];
__device__ __align__(128) bf16 g_klo[(size_t)NH * T_SEQ * HD];
__device__ __align__(128) bf16 g_vhi[(size_t)NH * T_SEQ * HD];
__device__ __align__(128) bf16 g_vlo[(size_t)NH * T_SEQ * HD];
__device__ __align__(128) bf16 g_ahi[(size_t)T_SEQ * C_EMB];
__device__ __align__(128) bf16 g_alo[(size_t)T_SEQ * C_EMB];

// ---------------------------------------------------------------------------
// Helpers (baseline PTX only — no 'a'-arch features)
// ---------------------------------------------------------------------------
__device__ __forceinline__ uint32_t smem_u32(const void* p) {
    uint32_t a;
    asm("{ .reg .u64 t; cvta.to.shared.u64 t, %1; cvt.u32.u64 %0, t; }"
        : "=r"(a) : "l"(p));
    return a;
}
__device__ __forceinline__ void ldm4(uint32_t addr, uint32_t* r) {
    asm volatile("ldmatrix.sync.aligned.m8n8.x4.shared.b16 {%0,%1,%2,%3}, [%4];"
                 : "=r"(r[0]), "=r"(r[1]), "=r"(r[2]), "=r"(r[3]) : "r"(addr));
}
__device__ __forceinline__ void ldm4t(uint32_t addr, uint32_t* r) {
    asm volatile("ldmatrix.sync.aligned.m8n8.x4.trans.shared.b16 {%0,%1,%2,%3}, [%4];"
                 : "=r"(r[0]), "=r"(r[1]), "=r"(r[2]), "=r"(r[3]) : "r"(addr));
}
__device__ __forceinline__ void mma16816(float* d, const uint32_t* a,
                                         const uint32_t* b) {
    asm volatile(
        "mma.sync.aligned.m16n8k16.row.col.f32.bf16.bf16.f32 "
        "{%0,%1,%2,%3}, {%4,%5,%6,%7}, {%8,%9}, {%0,%1,%2,%3};"
        : "+f"(d[0]), "+f"(d[1]), "+f"(d[2]), "+f"(d[3])
        : "r"(a[0]), "r"(a[1]), "r"(a[2]), "r"(a[3]), "r"(b[0]), "r"(b[1]));
}
__device__ __forceinline__ float ex2(float x) {
    float y;
    asm("ex2.approx.f32 %0, %1;" : "=f"(y) : "f"(x));
    return y;
}
__device__ __forceinline__ void hilo2(float v0, float v1, uint32_t& h, uint32_t& l) {
    bf162 hh, ll;
    hh.x = __float2bfloat16(v0); hh.y = __float2bfloat16(v1);
    ll.x = __float2bfloat16(v0 - __bfloat162float(hh.x));
    ll.y = __float2bfloat16(v1 - __bfloat162float(hh.y));
    h = *reinterpret_cast<uint32_t*>(&hh);
    l = *reinterpret_cast<uint32_t*>(&ll);
}
#define CP16(dst, src) \
    asm volatile("cp.async.cg.shared.global [%0], [%1], 16;" \
                 :: "r"(dst), "l"(src) : "memory")
#define CPCOMMIT() asm volatile("cp.async.commit_group;" ::: "memory")
#define CPWAIT0() asm volatile("cp.async.wait_group 0;" ::: "memory")
#define CPWAIT1() asm volatile("cp.async.wait_group 1;" ::: "memory")

// ---------------------------------------------------------------------------
// fp32 -> bf16 (hi, lo) split: x and all 4 weights in one launch
// ---------------------------------------------------------------------------
__global__ __launch_bounds__(256) void split_all(const float* __restrict__ x,
                                                 const float* __restrict__ w0,
                                                 const float* __restrict__ w1,
                                                 const float* __restrict__ w2,
                                                 const float* __restrict__ w3) {
    int i = blockIdx.x * 256 + threadIdx.x;
    const float* src;
    uint32_t *hp, *lp;
    int j;
    if (i < NX4) {
        src = x; j = i;
        hp = (uint32_t*)g_xhi; lp = (uint32_t*)g_xlo;
    } else {
        int t = i - NX4;
        int m = t / NW4;
        if (m >= 4) return;
        j = t - m * NW4;
        src = (m == 0) ? w0 : (m == 1) ? w1 : (m == 2) ? w2 : w3;
        hp = (uint32_t*)(g_whi[m]); lp = (uint32_t*)(g_wlo[m]);
    }
    float4 v = ((const float4*)src)[j];
    uint32_t h0, l0, h1, l1;
    hilo2(v.x, v.y, h0, l0);
    hilo2(v.z, v.w, h1, l1);
    hp[j * 2 + 0] = h0; hp[j * 2 + 1] = h1;
    lp[j * 2 + 0] = l0; lp[j * 2 + 1] = l1;
}

// ---------------------------------------------------------------------------
// Tensor GEMM: C[t,o] = sum_c X[t,c] * W[o,c], hi/lo split operands.
// CTA 128x128, 8 warps (4m x 2n). k-chunk 32, DOUBLE-BUFFERED cp.async
// pipeline (2 stages x 40960 B = 81920 B smem -> 2 CTAs/SM).
// stage layout: AH @0 AL @10240 BH @20480 BL @30720, row stride 40 bf16.
// ---------------------------------------------------------------------------
#define GS2 40
#define G2AL 10240
#define G2BH 20480
#define G2BL 30720
#define G2STG 40960
#define GEMM_SMEM 81920
#define NST2 (C_EMB / 32)     // 24

__global__ __launch_bounds__(256, 2) void gemm_tc(
    const bf16* __restrict__ Ahi, const bf16* __restrict__ Alo,
    const bf16* __restrict__ BhiB, const bf16* __restrict__ BloB,
    float* __restrict__ outf) {
    extern __shared__ bf16 smg[];
    const uint32_t sb = smem_u32(smg);
    const int tid = threadIdx.x, lane = tid & 31, wid = tid >> 5;
    const int wm = wid & 3, wn = wid >> 2;
    const int row0 = blockIdx.x * 128, col0 = blockIdx.y * 128;
    const int z = blockIdx.z;
    const bf16* Bhi = BhiB + (size_t)z * C_EMB * C_EMB;
    const bf16* Blo = BloB + (size_t)z * C_EMB * C_EMB;
    const int g = lane >> 3, lr = lane & 7;

    float acc[2][8][4];
#pragma unroll
    for (int i = 0; i < 2; i++)
#pragma unroll
        for (int j = 0; j < 8; j++)
#pragma unroll
            for (int c = 0; c < 4; c++) acc[i][j][c] = 0.f;

    auto pf = [&](int ks2, uint32_t bo2) {
        int k0 = ks2 * 32;
#pragma unroll
        for (int itr = 0; itr < 2; itr++) {
            int idx = tid + itr * 256;         // 0..511
            int r = idx >> 2, q = idx & 3;
            size_t ga = (size_t)(row0 + r) * C_EMB + k0 + q * 8;
            size_t gb = (size_t)(col0 + r) * C_EMB + k0 + q * 8;
            uint32_t so = (uint32_t)((r * GS2 + q * 8) * 2);
            CP16(sb + bo2 + so,         Ahi + ga);
            CP16(sb + bo2 + G2AL + so,  Alo + ga);
            CP16(sb + bo2 + G2BH + so,  Bhi + gb);
            CP16(sb + bo2 + G2BL + so,  Blo + gb);
        }
    };

    pf(0, 0u);
    CPCOMMIT();

    for (int ks = 0; ks < NST2; ks++) {
        const uint32_t bo = (ks & 1) ? (uint32_t)G2STG : 0u;
        if (ks + 1 < NST2) {
            pf(ks + 1, ((ks + 1) & 1) ? (uint32_t)G2STG : 0u);
            CPCOMMIT();
            CPWAIT1();
        } else {
            CPWAIT0();
        }
        __syncthreads();

#pragma unroll
        for (int kt = 0; kt < 2; kt++) {
            uint32_t ah[2][4], al[2][4];
#pragma unroll
            for (int mt = 0; mt < 2; mt++) {
                uint32_t aoff = (uint32_t)(((wm * 32 + mt * 16 + lr + (g & 1) * 8) * GS2 +
                                            kt * 16 + (g >> 1) * 8) * 2);
                ldm4(sb + bo + aoff, ah[mt]);
                ldm4(sb + bo + G2AL + aoff, al[mt]);
            }
#pragma unroll
            for (int np = 0; np < 4; np++) {
                uint32_t boff = (uint32_t)(((wn * 64 + np * 16 + lr + (g >> 1) * 8) * GS2 +
                                            kt * 16 + (g & 1) * 8) * 2);
                uint32_t bh[4], bl[4];
                ldm4(sb + bo + G2BH + boff, bh);
                ldm4(sb + bo + G2BL + boff, bl);
#pragma unroll
                for (int mt = 0; mt < 2; mt++) {
                    mma16816(acc[mt][2 * np],     ah[mt], &bh[0]);
                    mma16816(acc[mt][2 * np + 1], ah[mt], &bh[2]);
                    mma16816(acc[mt][2 * np],     ah[mt], &bl[0]);
                    mma16816(acc[mt][2 * np + 1], ah[mt], &bl[2]);
                    mma16816(acc[mt][2 * np],     al[mt], &bh[0]);
                    mma16816(acc[mt][2 * np + 1], al[mt], &bh[2]);
                }
            }
        }
        __syncthreads();
    }

    const int r = lane >> 2, cq = (lane & 3) * 2;
    bf16* Dhi = (z == 0) ? g_qhi : (z == 1) ? g_khi : g_vhi;
    bf16* Dlo = (z == 0) ? g_qlo : (z == 1) ? g_klo : g_vlo;
#pragma unroll
    for (int mt = 0; mt < 2; mt++) {
#pragma unroll
        for (int nt = 0; nt < 8; nt++) {
            int grow = row0 + wm * 32 + mt * 16 + r;
            int gc = col0 + wn * 64 + nt * 8 + cq;
            if (outf) {
                *(float2*)(outf + (size_t)grow * C_EMB + gc) =
                    make_float2(acc[mt][nt][0], acc[mt][nt][1]);
                *(float2*)(outf + (size_t)(grow + 8) * C_EMB + gc) =
                    make_float2(acc[mt][nt][2], acc[mt][nt][3]);
            } else {
                uint32_t h0, l0, h1, l1;
                hilo2(acc[mt][nt][0], acc[mt][nt][1], h0, l0);
                hilo2(acc[mt][nt][2], acc[mt][nt][3], h1, l1);
                int hh = gc >> 6, d = gc & 63;
                size_t b0 = ((size_t)hh * T_SEQ + grow) * HD + d;
                size_t b1 = ((size_t)hh * T_SEQ + grow + 8) * HD + d;
                *(uint32_t*)(Dhi + b0) = h0;
                *(uint32_t*)(Dlo + b0) = l0;
                *(uint32_t*)(Dhi + b1) = h1;
                *(uint32_t*)(Dlo + b1) = l1;
            }
        }
    }
}

// ---------------------------------------------------------------------------
// Tensor flash attention, causal. BLOCK_M=128 (8 warps x m16), BLOCK_N=64.
// Double-buffered cp.async KV pipeline; Q in its own smem region.
// exp2-domain softmax; fully-masked warp-tiles skipped.
// stage: KH=+0 KL=+9216 VH=+18432 VL=+27648 (36864 B); Q @73728/92160.
// ---------------------------------------------------------------------------
#define AS  72
#define STG 36864
#define AVHO 18432
#define AVLO 27648
#define AQH 73728
#define AQL 92160
#define ATTN_SMEM 110592

__global__ __launch_bounds__(256, 2) void attn_tc() {
    extern __shared__ char smc[];
    const uint32_t sb = smem_u32(smc);
    const int tid = threadIdx.x, lane = tid & 31, wid = tid >> 5;
    const int g = lane >> 3, lr = lane & 7;
    const int itc = gridDim.x - 1 - blockIdx.x;   // heavy first
    const int h = blockIdx.y;
    const int q0 = itc * 128;
    const int ntiles = 2 * itc + 2;               // KV tiles of 64

    const bf16* Qh = g_qhi + (size_t)h * T_SEQ * HD;
    const bf16* Ql = g_qlo + (size_t)h * T_SEQ * HD;
    const bf16* Kh = g_khi + (size_t)h * T_SEQ * HD;
    const bf16* Kl = g_klo + (size_t)h * T_SEQ * HD;
    const bf16* Vh = g_vhi + (size_t)h * T_SEQ * HD;
    const bf16* Vl = g_vlo + (size_t)h * T_SEQ * HD;

    // Q tile -> dedicated smem region (cp.async, first commit group)
#pragma unroll
    for (int itr = 0; itr < 4; itr++) {
        int idx = tid + itr * 256;
        int r = idx >> 3, q = idx & 7;
        uint32_t so = (uint32_t)((r * AS + q * 8) * 2);
        size_t gofs = (size_t)(q0 + r) * HD + q * 8;
        CP16(sb + AQH + so, Qh + gofs);
        CP16(sb + AQL + so, Ql + gofs);
    }

    auto prefetch = [&](int jt2, uint32_t bo) {
        int k0b = jt2 * 64;
#pragma unroll
        for (int itr = 0; itr < 2; itr++) {
            int idx = tid + itr * 256;
            int r = idx >> 3, q = idx & 7;
            uint32_t so = (uint32_t)((r * AS + q * 8) * 2);
            size_t gofs = (size_t)(k0b + r) * HD + q * 8;
            CP16(sb + bo + so,          Kh + gofs);
            CP16(sb + bo + 9216 + so,   Kl + gofs);
            CP16(sb + bo + AVHO + so,   Vh + gofs);
            CP16(sb + bo + AVLO + so,   Vl + gofs);
        }
    };

    float m[2] = {-INFINITY, -INFINITY}, lsum[2] = {0.f, 0.f};
    float ov[8][4];
#pragma unroll
    for (int i = 0; i < 8; i++)
#pragma unroll
        for (int c = 0; c < 4; c++) ov[i][c] = 0.f;

    prefetch(0, 0u);      // Q + stage0 in group 0
    CPCOMMIT();

    const uint32_t qoff_base = (uint32_t)(((wid * 16 + lr + (g & 1) * 8) * AS +
                                           (g >> 1) * 8) * 2);

    for (int jt = 0; jt < ntiles; jt++) {
        const uint32_t bo = (jt & 1) ? (uint32_t)STG : 0u;
        if (jt + 1 < ntiles) {
            prefetch(jt + 1, ((jt + 1) & 1) ? (uint32_t)STG : 0u);
            CPCOMMIT();
            CPWAIT1();
        } else {
            CPWAIT0();
        }
        __syncthreads();

        const int k0b = jt * 64;
        // warp rows [q0+wid*16, +15]; 16-row warps align with 64-col tiles:
        // either all rows >= k0b or all < k0b (fully masked -> skip compute)
        const bool skip = (wid * 16 + 15) < (k0b - q0);
        if (!skip) {
            // S = Q K^T  (Q frags re-loaded per k-step)
            float sv[8][4];
#pragma unroll
            for (int i = 0; i < 8; i++)
#pragma unroll
                for (int c = 0; c < 4; c++) sv[i][c] = 0.f;
#pragma unroll
            for (int kt = 0; kt < 4; kt++) {
                uint32_t qfh[4], qfl[4];
                uint32_t qa = qoff_base + (uint32_t)(kt * 32);
                ldm4(sb + AQH + qa, qfh);
                ldm4(sb + AQL + qa, qfl);
#pragma unroll
                for (int np = 0; np < 4; np++) {
                    uint32_t boff = (uint32_t)(((np * 16 + lr + (g >> 1) * 8) * AS +
                                                kt * 16 + (g & 1) * 8) * 2);
                    uint32_t bh[4], bl[4];
                    ldm4(sb + bo + boff, bh);
                    ldm4(sb + bo + 9216 + boff, bl);
                    mma16816(sv[2 * np],     qfh, &bh[0]);
                    mma16816(sv[2 * np + 1], qfh, &bh[2]);
                    mma16816(sv[2 * np],     qfh, &bl[0]);
                    mma16816(sv[2 * np + 1], qfh, &bl[2]);
                    mma16816(sv[2 * np],     qfl, &bh[0]);
                    mma16816(sv[2 * np + 1], qfl, &bh[2]);
                }
            }

            // scale into log2 domain + causal mask
            const float scl2 = 0.18033688f;   // 0.125 * log2(e)
            const int rbase = q0 + wid * 16 + (lane >> 2);
            const bool diag = (k0b + 63) > (q0 + wid * 16);
#pragma unroll
            for (int nt = 0; nt < 8; nt++) {
#pragma unroll
                for (int c = 0; c < 4; c++) {
                    float s = sv[nt][c] * scl2;
                    if (diag) {
                        int row = rbase + ((c >> 1) << 3);
                        int col = k0b + nt * 8 + (lane & 3) * 2 + (c & 1);
                        if (col > row) s = -INFINITY;
                    }
                    sv[nt][c] = s;
                }
            }
            // online softmax (exp2 domain)
#pragma unroll
            for (int half = 0; half < 2; half++) {
                int ci = half * 2;
                float mt = -INFINITY;
#pragma unroll
                for (int nt = 0; nt < 8; nt++)
                    mt = fmaxf(mt, fmaxf(sv[nt][ci], sv[nt][ci + 1]));
                mt = fmaxf(mt, __shfl_xor_sync(0xffffffffu, mt, 1));
                mt = fmaxf(mt, __shfl_xor_sync(0xffffffffu, mt, 2));
                float mn = fmaxf(m[half], mt);
                float corr = ex2(m[half] - mn);
                m[half] = mn;
                float rs = 0.f;
#pragma unroll
                for (int nt = 0; nt < 8; nt++) {
                    float p0 = ex2(sv[nt][ci] - mn);
                    float p1 = ex2(sv[nt][ci + 1] - mn);
                    sv[nt][ci] = p0; sv[nt][ci + 1] = p1;
                    rs += p0 + p1;
                }
                rs += __shfl_xor_sync(0xffffffffu, rs, 1);
                rs += __shfl_xor_sync(0xffffffffu, rs, 2);
                lsum[half] = lsum[half] * corr + rs;
#pragma unroll
                for (int dn = 0; dn < 8; dn++) {
                    ov[dn][ci] *= corr;
                    ov[dn][ci + 1] *= corr;
                }
            }

            // O += P V  (V fragments via ldmatrix.trans on row-major V)
#pragma unroll
            for (int kt = 0; kt < 4; kt++) {
                uint32_t pfh[4], pfl[4];
                hilo2(sv[2 * kt][0],     sv[2 * kt][1],     pfh[0], pfl[0]);
                hilo2(sv[2 * kt][2],     sv[2 * kt][3],     pfh[1], pfl[1]);
                hilo2(sv[2 * kt + 1][0], sv[2 * kt + 1][1], pfh[2], pfl[2]);
                hilo2(sv[2 * kt + 1][2], sv[2 * kt + 1][3], pfh[3], pfl[3]);
#pragma unroll
                for (int dp = 0; dp < 4; dp++) {
                    uint32_t vaddr = (uint32_t)(((kt * 16 + (lane & 15)) * AS +
                                                 dp * 16 + (lane >> 4) * 8) * 2);
                    uint32_t vfh[4], vfl[4];
                    ldm4t(sb + bo + AVHO + vaddr, vfh);
                    ldm4t(sb + bo + AVLO + vaddr, vfl);
                    mma16816(ov[2 * dp],     pfh, &vfh[0]);
                    mma16816(ov[2 * dp + 1], pfh, &vfh[2]);
                    mma16816(ov[2 * dp],     pfh, &vfl[0]);
                    mma16816(ov[2 * dp + 1], pfh, &vfl[2]);
                    mma16816(ov[2 * dp],     pfl, &vfh[0]);
                    mma16816(ov[2 * dp + 1], pfl, &vfh[2]);
                }
            }
        }
        __syncthreads();
    }

    // epilogue: normalize, split hi/lo, write att [T, 768]
    const int r = lane >> 2, cq = (lane & 3) * 2;
#pragma unroll
    for (int half = 0; half < 2; half++) {
        float inv = 1.f / lsum[half];
        int rg = q0 + wid * 16 + r + half * 8;
#pragma unroll
        for (int dn = 0; dn < 8; dn++) {
            float v0 = ov[dn][half * 2] * inv;
            float v1 = ov[dn][half * 2 + 1] * inv;
            uint32_t hh, ll;
            hilo2(v0, v1, hh, ll);
            size_t base = (size_t)rg * C_EMB + h * HD + dn * 8 + cq;
            *(uint32_t*)(g_ahi + base) = hh;
            *(uint32_t*)(g_alo + base) = ll;
        }
    }
}

// ---------------------------------------------------------------------------
extern "C" void kernel_launch(void* const* d_in, const int* in_sizes, int n_in,
                              void* d_out, int out_size) {
    (void)in_sizes; (void)n_in; (void)out_size;
    const float* x  = (const float*)d_in[0];
    const float* wq = (const float*)d_in[1];
    const float* wk = (const float*)d_in[2];
    const float* wv = (const float*)d_in[3];
    const float* wo = (const float*)d_in[4];
    float* out = (float*)d_out;

    bf16 *xhi, *xlo, *whi, *wlo, *ahi, *alo;
    cudaGetSymbolAddress((void**)&xhi, g_xhi);
    cudaGetSymbolAddress((void**)&xlo, g_xlo);
    cudaGetSymbolAddress((void**)&whi, g_whi);
    cudaGetSymbolAddress((void**)&wlo, g_wlo);
    cudaGetSymbolAddress((void**)&ahi, g_ahi);
    cudaGetSymbolAddress((void**)&alo, g_alo);
    cudaFuncSetAttribute(gemm_tc, cudaFuncAttributeMaxDynamicSharedMemorySize,
                         GEMM_SMEM);
    cudaFuncSetAttribute(attn_tc, cudaFuncAttributeMaxDynamicSharedMemorySize,
                         ATTN_SMEM);
    const size_t WSZ = (size_t)C_EMB * C_EMB;

    int ntot = NX4 + 4 * NW4;
    split_all<<<(ntot + 255) / 256, 256>>>(x, wq, wk, wv, wo);

    dim3 ggrid(T_SEQ / 128, C_EMB / 128, 3);   // fused QKV: 576 CTAs
    gemm_tc<<<ggrid, 256, GEMM_SMEM>>>(xhi, xlo, whi, wlo, nullptr);

    dim3 agrid(T_SEQ / 128, NH);               // 32 x 12
    attn_tc<<<agrid, 256, ATTN_SMEM>>>();

    dim3 ogrid(T_SEQ / 128, C_EMB / 128, 1);
    gemm_tc<<<ogrid, 256, GEMM_SMEM>>>(ahi, alo, whi + 3 * WSZ, wlo + 3 * WSZ, out);
}

// round 10
// speedup vs baseline: 1.0224x; 1.0224x over previous
#include <cuda_runtime.h>
#include <cuda_bf16.h>
#include <math.h>
#include <stdint.h>

#define T_SEQ 4096
#define C_EMB 768
#define NH    12
#define HD    64
#define NW4   147456          // (768*768)/4
#define NX4   786432          // (4096*768)/4

typedef __nv_bfloat16 bf16;
typedef __nv_bfloat162 bf162;

// ---------------------------------------------------------------------------
// Scratch (__device__ globals — allocation-guard-safe)
// ---------------------------------------------------------------------------
__device__ __align__(128) bf16 g_xhi[(size_t)T_SEQ * C_EMB];
__device__ __align__(128) bf16 g_xlo[(size_t)T_SEQ * C_EMB];
__device__ __align__(128) bf16 g_whi[4][(size_t)C_EMB * C_EMB];
__device__ __align__(128) bf16 g_wlo[4][(size_t)C_EMB * C_EMB];
__device__ __align__(128) bf16 g_qhi[(size_t)NH * T_SEQ * HD];
__device__ __align__(128) bf16 g_qlo[(size_t)NH * T_SEQ * HD];
__device__ __align__(128) bf16 g_khi[(size_t)NH * T_SEQ * HD];
__device__ __align__(128) bf16 g_klo[(size_t)NH * T_SEQ * HD];
__device__ __align__(128) bf16 g_vhi[(size_t)NH * T_SEQ * HD];
__device__ __align__(128) bf16 g_vlo[(size_t)NH * T_SEQ * HD];
__device__ __align__(128) bf16 g_ahi[(size_t)T_SEQ * C_EMB];
__device__ __align__(128) bf16 g_alo[(size_t)T_SEQ * C_EMB];

// ---------------------------------------------------------------------------
// Helpers (baseline PTX only — no 'a'-arch features)
// ---------------------------------------------------------------------------
__device__ __forceinline__ uint32_t smem_u32(const void* p) {
    uint32_t a;
    asm("{ .reg .u64 t; cvta.to.shared.u64 t, %1; cvt.u32.u64 %0, t; }"
        : "=r"(a) : "l"(p));
    return a;
}
__device__ __forceinline__ void ldm4(uint32_t addr, uint32_t* r) {
    asm volatile("ldmatrix.sync.aligned.m8n8.x4.shared.b16 {%0,%1,%2,%3}, [%4];"
                 : "=r"(r[0]), "=r"(r[1]), "=r"(r[2]), "=r"(r[3]) : "r"(addr));
}
__device__ __forceinline__ void ldm4t(uint32_t addr, uint32_t* r) {
    asm volatile("ldmatrix.sync.aligned.m8n8.x4.trans.shared.b16 {%0,%1,%2,%3}, [%4];"
                 : "=r"(r[0]), "=r"(r[1]), "=r"(r[2]), "=r"(r[3]) : "r"(addr));
}
__device__ __forceinline__ void mma16816(float* d, const uint32_t* a,
                                         const uint32_t* b) {
    asm volatile(
        "mma.sync.aligned.m16n8k16.row.col.f32.bf16.bf16.f32 "
        "{%0,%1,%2,%3}, {%4,%5,%6,%7}, {%8,%9}, {%0,%1,%2,%3};"
        : "+f"(d[0]), "+f"(d[1]), "+f"(d[2]), "+f"(d[3])
        : "r"(a[0]), "r"(a[1]), "r"(a[2]), "r"(a[3]), "r"(b[0]), "r"(b[1]));
}
__device__ __forceinline__ float ex2(float x) {
    float y;
    asm("ex2.approx.f32 %0, %1;" : "=f"(y) : "f"(x));
    return y;
}
__device__ __forceinline__ void hilo2(float v0, float v1, uint32_t& h, uint32_t& l) {
    bf162 hh, ll;
    hh.x = __float2bfloat16(v0); hh.y = __float2bfloat16(v1);
    ll.x = __float2bfloat16(v0 - __bfloat162float(hh.x));
    ll.y = __float2bfloat16(v1 - __bfloat162float(hh.y));
    h = *reinterpret_cast<uint32_t*>(&hh);
    l = *reinterpret_cast<uint32_t*>(&ll);
}
#define CP16(dst, src) \
    asm volatile("cp.async.cg.shared.global [%0], [%1], 16;" \
                 :: "r"(dst), "l"(src) : "memory")
#define CPCOMMIT() asm volatile("cp.async.commit_group;" ::: "memory")
#define CPWAIT0() asm volatile("cp.async.wait_group 0;" ::: "memory")
#define CPWAIT1() asm volatile("cp.async.wait_group 1;" ::: "memory")

// ---------------------------------------------------------------------------
// fp32 -> bf16 (hi, lo) split: x and all 4 weights in one launch
// ---------------------------------------------------------------------------
__global__ __launch_bounds__(256) void split_all(const float* __restrict__ x,
                                                 const float* __restrict__ w0,
                                                 const float* __restrict__ w1,
                                                 const float* __restrict__ w2,
                                                 const float* __restrict__ w3) {
    int i = blockIdx.x * 256 + threadIdx.x;
    const float* src;
    uint32_t *hp, *lp;
    int j;
    if (i < NX4) {
        src = x; j = i;
        hp = (uint32_t*)g_xhi; lp = (uint32_t*)g_xlo;
    } else {
        int t = i - NX4;
        int m = t / NW4;
        if (m >= 4) return;
        j = t - m * NW4;
        src = (m == 0) ? w0 : (m == 1) ? w1 : (m == 2) ? w2 : w3;
        hp = (uint32_t*)(g_whi[m]); lp = (uint32_t*)(g_wlo[m]);
    }
    float4 v = ((const float4*)src)[j];
    uint32_t h0, l0, h1, l1;
    hilo2(v.x, v.y, h0, l0);
    hilo2(v.z, v.w, h1, l1);
    hp[j * 2 + 0] = h0; hp[j * 2 + 1] = h1;
    lp[j * 2 + 0] = l0; lp[j * 2 + 1] = l1;
}

// ---------------------------------------------------------------------------
// Tensor GEMM: C[t,o] = sum_c X[t,c] * W[o,c], hi/lo split operands.
// CTA tile 128x64, 8 warps (each 16 rows x 64 cols). k-chunk 64,
// double-buffered cp.async (2 stages x 55296 B = 110592 B -> 2 CTAs/SM).
// stage layout: AH @0 (128x72) AL @18432 BH @36864 (64x72) BL @46080.
// z selects weight; outf != 0: fp32 out; else bf16 hi/lo head-major by z.
// ---------------------------------------------------------------------------
#define GS 72
#define GAL 18432
#define GBH 36864
#define GBL 46080
#define GSTG 55296
#define GEMM_SMEM 110592
#define NSTG (C_EMB / 64)     // 12

__global__ __launch_bounds__(256, 2) void gemm_tc(
    const bf16* __restrict__ Ahi, const bf16* __restrict__ Alo,
    const bf16* __restrict__ BhiB, const bf16* __restrict__ BloB,
    float* __restrict__ outf) {
    extern __shared__ bf16 smg[];
    const uint32_t sb = smem_u32(smg);
    const int tid = threadIdx.x, lane = tid & 31, wid = tid >> 5;
    const int row0 = blockIdx.x * 128;
    const int cy = blockIdx.y;            // 64-col tile == head for QKV
    const int col0 = cy * 64;
    const int z = blockIdx.z;
    const bf16* Bhi = BhiB + (size_t)z * C_EMB * C_EMB;
    const bf16* Blo = BloB + (size_t)z * C_EMB * C_EMB;
    const int g = lane >> 3, lr = lane & 7;

    float acc[8][4];
#pragma unroll
    for (int j = 0; j < 8; j++)
#pragma unroll
        for (int c = 0; c < 4; c++) acc[j][c] = 0.f;

    auto pf = [&](int s, uint32_t bo) {
        int k0 = s * 64;
#pragma unroll
        for (int itr = 0; itr < 4; itr++) {       // A: 128 rows
            int idx = tid + itr * 256;            // 0..1023
            int r = idx >> 3, q = idx & 7;
            uint32_t so = (uint32_t)((r * GS + q * 8) * 2);
            size_t ga = (size_t)(row0 + r) * C_EMB + k0 + q * 8;
            CP16(sb + bo + so,       Ahi + ga);
            CP16(sb + bo + GAL + so, Alo + ga);
        }
#pragma unroll
        for (int itr = 0; itr < 2; itr++) {       // B: 64 rows
            int idx = tid + itr * 256;            // 0..511
            int r = idx >> 3, q = idx & 7;
            uint32_t so = (uint32_t)((r * GS + q * 8) * 2);
            size_t gb = (size_t)(col0 + r) * C_EMB + k0 + q * 8;
            CP16(sb + bo + GBH + so, Bhi + gb);
            CP16(sb + bo + GBL + so, Blo + gb);
        }
    };

    pf(0, 0u);
    CPCOMMIT();

    for (int s = 0; s < NSTG; s++) {
        const uint32_t bo = (s & 1) ? (uint32_t)GSTG : 0u;
        if (s + 1 < NSTG) {
            pf(s + 1, ((s + 1) & 1) ? (uint32_t)GSTG : 0u);
            CPCOMMIT();
            CPWAIT1();
        } else {
            CPWAIT0();
        }
        __syncthreads();

#pragma unroll
        for (int kt = 0; kt < 4; kt++) {
            uint32_t ah[4], al[4];
            uint32_t aoff = (uint32_t)(((wid * 16 + lr + (g & 1) * 8) * GS +
                                        kt * 16 + (g >> 1) * 8) * 2);
            ldm4(sb + bo + aoff, ah);
            ldm4(sb + bo + GAL + aoff, al);
#pragma unroll
            for (int np = 0; np < 4; np++) {
                uint32_t boff = (uint32_t)(((np * 16 + lr + (g >> 1) * 8) * GS +
                                            kt * 16 + (g & 1) * 8) * 2);
                uint32_t bh[4], bl[4];
                ldm4(sb + bo + GBH + boff, bh);
                ldm4(sb + bo + GBL + boff, bl);
                mma16816(acc[2 * np],     ah, &bh[0]);
                mma16816(acc[2 * np + 1], ah, &bh[2]);
                mma16816(acc[2 * np],     ah, &bl[0]);
                mma16816(acc[2 * np + 1], ah, &bl[2]);
                mma16816(acc[2 * np],     al, &bh[0]);
                mma16816(acc[2 * np + 1], al, &bh[2]);
            }
        }
        __syncthreads();
    }

    const int r = lane >> 2, cq = (lane & 3) * 2;
    const int grow = row0 + wid * 16 + r;
    bf16* Dhi = (z == 0) ? g_qhi : (z == 1) ? g_khi : g_vhi;
    bf16* Dlo = (z == 0) ? g_qlo : (z == 1) ? g_klo : g_vlo;
#pragma unroll
    for (int nt = 0; nt < 8; nt++) {
        int d = nt * 8 + cq;                       // 0..63 within col tile
        if (outf) {
            *(float2*)(outf + (size_t)grow * C_EMB + col0 + d) =
                make_float2(acc[nt][0], acc[nt][1]);
            *(float2*)(outf + (size_t)(grow + 8) * C_EMB + col0 + d) =
                make_float2(acc[nt][2], acc[nt][3]);
        } else {
            uint32_t h0, l0, h1, l1;
            hilo2(acc[nt][0], acc[nt][1], h0, l0);
            hilo2(acc[nt][2], acc[nt][3], h1, l1);
            size_t b0 = ((size_t)cy * T_SEQ + grow) * HD + d;
            size_t b1 = ((size_t)cy * T_SEQ + grow + 8) * HD + d;
            *(uint32_t*)(Dhi + b0) = h0;
            *(uint32_t*)(Dlo + b0) = l0;
            *(uint32_t*)(Dhi + b1) = h1;
            *(uint32_t*)(Dlo + b1) = l1;
        }
    }
}

// ---------------------------------------------------------------------------
// Tensor flash attention, causal. BLOCK_M=128 (8 warps x m16), BLOCK_N=64.
// Double-buffered cp.async KV pipeline; Q in its own smem region.
// exp2-domain softmax; fully-masked warp-tiles skipped.
// stage: KH=+0 KL=+9216 VH=+18432 VL=+27648 (36864 B); Q @73728/92160.
// ---------------------------------------------------------------------------
#define AS  72
#define STG 36864
#define AVHO 18432
#define AVLO 27648
#define AQH 73728
#define AQL 92160
#define ATTN_SMEM 110592

__global__ __launch_bounds__(256, 2) void attn_tc() {
    extern __shared__ char smc[];
    const uint32_t sb = smem_u32(smc);
    const int tid = threadIdx.x, lane = tid & 31, wid = tid >> 5;
    const int g = lane >> 3, lr = lane & 7;
    const int itc = gridDim.x - 1 - blockIdx.x;   // heavy first
    const int h = blockIdx.y;
    const int q0 = itc * 128;
    const int ntiles = 2 * itc + 2;               // KV tiles of 64

    const bf16* Qh = g_qhi + (size_t)h * T_SEQ * HD;
    const bf16* Ql = g_qlo + (size_t)h * T_SEQ * HD;
    const bf16* Kh = g_khi + (size_t)h * T_SEQ * HD;
    const bf16* Kl = g_klo + (size_t)h * T_SEQ * HD;
    const bf16* Vh = g_vhi + (size_t)h * T_SEQ * HD;
    const bf16* Vl = g_vlo + (size_t)h * T_SEQ * HD;

    // Q tile -> dedicated smem region (cp.async, first commit group)
#pragma unroll
    for (int itr = 0; itr < 4; itr++) {
        int idx = tid + itr * 256;
        int r = idx >> 3, q = idx & 7;
        uint32_t so = (uint32_t)((r * AS + q * 8) * 2);
        size_t gofs = (size_t)(q0 + r) * HD + q * 8;
        CP16(sb + AQH + so, Qh + gofs);
        CP16(sb + AQL + so, Ql + gofs);
    }

    auto prefetch = [&](int jt2, uint32_t bo) {
        int k0b = jt2 * 64;
#pragma unroll
        for (int itr = 0; itr < 2; itr++) {
            int idx = tid + itr * 256;
            int r = idx >> 3, q = idx & 7;
            uint32_t so = (uint32_t)((r * AS + q * 8) * 2);
            size_t gofs = (size_t)(k0b + r) * HD + q * 8;
            CP16(sb + bo + so,          Kh + gofs);
            CP16(sb + bo + 9216 + so,   Kl + gofs);
            CP16(sb + bo + AVHO + so,   Vh + gofs);
            CP16(sb + bo + AVLO + so,   Vl + gofs);
        }
    };

    float m[2] = {-INFINITY, -INFINITY}, lsum[2] = {0.f, 0.f};
    float ov[8][4];
#pragma unroll
    for (int i = 0; i < 8; i++)
#pragma unroll
        for (int c = 0; c < 4; c++) ov[i][c] = 0.f;

    prefetch(0, 0u);      // Q + stage0 in group 0
    CPCOMMIT();

    const uint32_t qoff_base = (uint32_t)(((wid * 16 + lr + (g & 1) * 8) * AS +
                                           (g >> 1) * 8) * 2);

    for (int jt = 0; jt < ntiles; jt++) {
        const uint32_t bo = (jt & 1) ? (uint32_t)STG : 0u;
        if (jt + 1 < ntiles) {
            prefetch(jt + 1, ((jt + 1) & 1) ? (uint32_t)STG : 0u);
            CPCOMMIT();
            CPWAIT1();
        } else {
            CPWAIT0();
        }
        __syncthreads();

        const int k0b = jt * 64;
        const bool skip = (wid * 16 + 15) < (k0b - q0);
        if (!skip) {
            // S = Q K^T  (Q frags re-loaded per k-step)
            float sv[8][4];
#pragma unroll
            for (int i = 0; i < 8; i++)
#pragma unroll
                for (int c = 0; c < 4; c++) sv[i][c] = 0.f;
#pragma unroll
            for (int kt = 0; kt < 4; kt++) {
                uint32_t qfh[4], qfl[4];
                uint32_t qa = qoff_base + (uint32_t)(kt * 32);
                ldm4(sb + AQH + qa, qfh);
                ldm4(sb + AQL + qa, qfl);
#pragma unroll
                for (int np = 0; np < 4; np++) {
                    uint32_t boff = (uint32_t)(((np * 16 + lr + (g >> 1) * 8) * AS +
                                                kt * 16 + (g & 1) * 8) * 2);
                    uint32_t bh[4], bl[4];
                    ldm4(sb + bo + boff, bh);
                    ldm4(sb + bo + 9216 + boff, bl);
                    mma16816(sv[2 * np],     qfh, &bh[0]);
                    mma16816(sv[2 * np + 1], qfh, &bh[2]);
                    mma16816(sv[2 * np],     qfh, &bl[0]);
                    mma16816(sv[2 * np + 1], qfh, &bl[2]);
                    mma16816(sv[2 * np],     qfl, &bh[0]);
                    mma16816(sv[2 * np + 1], qfl, &bh[2]);
                }
            }

            // scale into log2 domain + causal mask
            const float scl2 = 0.18033688f;   // 0.125 * log2(e)
            const int rbase = q0 + wid * 16 + (lane >> 2);
            const bool diag = (k0b + 63) > (q0 + wid * 16);
#pragma unroll
            for (int nt = 0; nt < 8; nt++) {
#pragma unroll
                for (int c = 0; c < 4; c++) {
                    float s = sv[nt][c] * scl2;
                    if (diag) {
                        int row = rbase + ((c >> 1) << 3);
                        int col = k0b + nt * 8 + (lane & 3) * 2 + (c & 1);
                        if (col > row) s = -INFINITY;
                    }
                    sv[nt][c] = s;
                }
            }
            // online softmax (exp2 domain)
#pragma unroll
            for (int half = 0; half < 2; half++) {
                int ci = half * 2;
                float mt = -INFINITY;
#pragma unroll
                for (int nt = 0; nt < 8; nt++)
                    mt = fmaxf(mt, fmaxf(sv[nt][ci], sv[nt][ci + 1]));
                mt = fmaxf(mt, __shfl_xor_sync(0xffffffffu, mt, 1));
                mt = fmaxf(mt, __shfl_xor_sync(0xffffffffu, mt, 2));
                float mn = fmaxf(m[half], mt);
                float corr = ex2(m[half] - mn);
                m[half] = mn;
                float rs = 0.f;
#pragma unroll
                for (int nt = 0; nt < 8; nt++) {
                    float p0 = ex2(sv[nt][ci] - mn);
                    float p1 = ex2(sv[nt][ci + 1] - mn);
                    sv[nt][ci] = p0; sv[nt][ci + 1] = p1;
                    rs += p0 + p1;
                }
                rs += __shfl_xor_sync(0xffffffffu, rs, 1);
                rs += __shfl_xor_sync(0xffffffffu, rs, 2);
                lsum[half] = lsum[half] * corr + rs;
#pragma unroll
                for (int dn = 0; dn < 8; dn++) {
                    ov[dn][ci] *= corr;
                    ov[dn][ci + 1] *= corr;
                }
            }

            // O += P V  (V fragments via ldmatrix.trans on row-major V)
#pragma unroll
            for (int kt = 0; kt < 4; kt++) {
                uint32_t pfh[4], pfl[4];
                hilo2(sv[2 * kt][0],     sv[2 * kt][1],     pfh[0], pfl[0]);
                hilo2(sv[2 * kt][2],     sv[2 * kt][3],     pfh[1], pfl[1]);
                hilo2(sv[2 * kt + 1][0], sv[2 * kt + 1][1], pfh[2], pfl[2]);
                hilo2(sv[2 * kt + 1][2], sv[2 * kt + 1][3], pfh[3], pfl[3]);
#pragma unroll
                for (int dp = 0; dp < 4; dp++) {
                    uint32_t vaddr = (uint32_t)(((kt * 16 + (lane & 15)) * AS +
                                                 dp * 16 + (lane >> 4) * 8) * 2);
                    uint32_t vfh[4], vfl[4];
                    ldm4t(sb + bo + AVHO + vaddr, vfh);
                    ldm4t(sb + bo + AVLO + vaddr, vfl);
                    mma16816(ov[2 * dp],     pfh, &vfh[0]);
                    mma16816(ov[2 * dp + 1], pfh, &vfh[2]);
                    mma16816(ov[2 * dp],     pfh, &vfl[0]);
                    mma16816(ov[2 * dp + 1], pfh, &vfl[2]);
                    mma16816(ov[2 * dp],     pfl, &vfh[0]);
                    mma16816(ov[2 * dp + 1], pfl, &vfh[2]);
                }
            }
        }
        __syncthreads();
    }

    // epilogue: normalize, split hi/lo, write att [T, 768]
    const int r = lane >> 2, cq = (lane & 3) * 2;
#pragma unroll
    for (int half = 0; half < 2; half++) {
        float inv = 1.f / lsum[half];
        int rg = q0 + wid * 16 + r + half * 8;
#pragma unroll
        for (int dn = 0; dn < 8; dn++) {
            float v0 = ov[dn][half * 2] * inv;
            float v1 = ov[dn][half * 2 + 1] * inv;
            uint32_t hh, ll;
            hilo2(v0, v1, hh, ll);
            size_t base = (size_t)rg * C_EMB + h * HD + dn * 8 + cq;
            *(uint32_t*)(g_ahi + base) = hh;
            *(uint32_t*)(g_alo + base) = ll;
        }
    }
}

// ---------------------------------------------------------------------------
extern "C" void kernel_launch(void* const* d_in, const int* in_sizes, int n_in,
                              void* d_out, int out_size) {
    (void)in_sizes; (void)n_in; (void)out_size;
    const float* x  = (const float*)d_in[0];
    const float* wq = (const float*)d_in[1];
    const float* wk = (const float*)d_in[2];
    const float* wv = (const float*)d_in[3];
    const float* wo = (const float*)d_in[4];
    float* out = (float*)d_out;

    bf16 *xhi, *xlo, *whi, *wlo, *ahi, *alo;
    cudaGetSymbolAddress((void**)&xhi, g_xhi);
    cudaGetSymbolAddress((void**)&xlo, g_xlo);
    cudaGetSymbolAddress((void**)&whi, g_whi);
    cudaGetSymbolAddress((void**)&wlo, g_wlo);
    cudaGetSymbolAddress((void**)&ahi, g_ahi);
    cudaGetSymbolAddress((void**)&alo, g_alo);
    cudaFuncSetAttribute(gemm_tc, cudaFuncAttributeMaxDynamicSharedMemorySize,
                         GEMM_SMEM);
    cudaFuncSetAttribute(attn_tc, cudaFuncAttributeMaxDynamicSharedMemorySize,
                         ATTN_SMEM);
    const size_t WSZ = (size_t)C_EMB * C_EMB;

    int ntot = NX4 + 4 * NW4;
    split_all<<<(ntot + 255) / 256, 256>>>(x, wq, wk, wv, wo);

    dim3 ggrid(T_SEQ / 128, C_EMB / 64, 3);    // fused QKV: 1152 CTAs
    gemm_tc<<<ggrid, 256, GEMM_SMEM>>>(xhi, xlo, whi, wlo, nullptr);

    dim3 agrid(T_SEQ / 128, NH);               // 32 x 12
    attn_tc<<<agrid, 256, ATTN_SMEM>>>();

    dim3 ogrid(T_SEQ / 128, C_EMB / 64, 1);    // WO: 384 CTAs
    gemm_tc<<<ogrid, 256, GEMM_SMEM>>>(ahi, alo, whi + 3 * WSZ, wlo + 3 * WSZ, out);
}

// round 12
// speedup vs baseline: 1.0407x; 1.0179x over previous
#include <cuda_runtime.h>
#include <cuda_bf16.h>
#include <math.h>
#include <stdint.h>

#define T_SEQ 4096
#define C_EMB 768
#define NH    12
#define HD    64
#define NW4   147456          // (768*768)/4
#define NX4   786432          // (4096*768)/4

typedef __nv_bfloat16 bf16;
typedef __nv_bfloat162 bf162;

// ---------------------------------------------------------------------------
// Scratch (__device__ globals — allocation-guard-safe)
// ---------------------------------------------------------------------------
__device__ __align__(128) bf16 g_xhi[(size_t)T_SEQ * C_EMB];
__device__ __align__(128) bf16 g_xlo[(size_t)T_SEQ * C_EMB];
__device__ __align__(128) bf16 g_whi[4][(size_t)C_EMB * C_EMB];
__device__ __align__(128) bf16 g_wlo[4][(size_t)C_EMB * C_EMB];
__device__ __align__(128) bf16 g_qhi[(size_t)NH * T_SEQ * HD];
__device__ __align__(128) bf16 g_qlo[(size_t)NH * T_SEQ * HD];
__device__ __align__(128) bf16 g_khi[(size_t)NH * T_SEQ * HD];
__device__ __align__(128) bf16 g_klo[(size_t)NH * T_SEQ * HD];
__device__ __align__(128) bf16 g_vhi[(size_t)NH * T_SEQ * HD];
__device__ __align__(128) bf16 g_vlo[(size_t)NH * T_SEQ * HD];
__device__ __align__(128) bf16 g_ahi[(size_t)T_SEQ * C_EMB];
__device__ __align__(128) bf16 g_alo[(size_t)T_SEQ * C_EMB];

// ---------------------------------------------------------------------------
// Helpers (baseline PTX only — no 'a'-arch features)
// ---------------------------------------------------------------------------
__device__ __forceinline__ uint32_t smem_u32(const void* p) {
    uint32_t a;
    asm("{ .reg .u64 t; cvta.to.shared.u64 t, %1; cvt.u32.u64 %0, t; }"
        : "=r"(a) : "l"(p));
    return a;
}
__device__ __forceinline__ void ldm4(uint32_t addr, uint32_t* r) {
    asm volatile("ldmatrix.sync.aligned.m8n8.x4.shared.b16 {%0,%1,%2,%3}, [%4];"
                 : "=r"(r[0]), "=r"(r[1]), "=r"(r[2]), "=r"(r[3]) : "r"(addr));
}
__device__ __forceinline__ void ldm4t(uint32_t addr, uint32_t* r) {
    asm volatile("ldmatrix.sync.aligned.m8n8.x4.trans.shared.b16 {%0,%1,%2,%3}, [%4];"
                 : "=r"(r[0]), "=r"(r[1]), "=r"(r[2]), "=r"(r[3]) : "r"(addr));
}
__device__ __forceinline__ void mma16816(float* d, const uint32_t* a,
                                         const uint32_t* b) {
    asm volatile(
        "mma.sync.aligned.m16n8k16.row.col.f32.bf16.bf16.f32 "
        "{%0,%1,%2,%3}, {%4,%5,%6,%7}, {%8,%9}, {%0,%1,%2,%3};"
        : "+f"(d[0]), "+f"(d[1]), "+f"(d[2]), "+f"(d[3])
        : "r"(a[0]), "r"(a[1]), "r"(a[2]), "r"(a[3]), "r"(b[0]), "r"(b[1]));
}
__device__ __forceinline__ float ex2(float x) {
    float y;
    asm("ex2.approx.f32 %0, %1;" : "=f"(y) : "f"(x));
    return y;
}
__device__ __forceinline__ void hilo2(float v0, float v1, uint32_t& h, uint32_t& l) {
    bf162 hh, ll;
    hh.x = __float2bfloat16(v0); hh.y = __float2bfloat16(v1);
    ll.x = __float2bfloat16(v0 - __bfloat162float(hh.x));
    ll.y = __float2bfloat16(v1 - __bfloat162float(hh.y));
    h = *reinterpret_cast<uint32_t*>(&hh);
    l = *reinterpret_cast<uint32_t*>(&ll);
}
#define CP16(dst, src) \
    asm volatile("cp.async.cg.shared.global [%0], [%1], 16;" \
                 :: "r"(dst), "l"(src) : "memory")
#define CPCOMMIT() asm volatile("cp.async.commit_group;" ::: "memory")
#define CPWAIT0() asm volatile("cp.async.wait_group 0;" ::: "memory")

// ---------------------------------------------------------------------------
// fp32 -> bf16 (hi, lo) split: x and all 4 weights in one launch
// ---------------------------------------------------------------------------
__global__ __launch_bounds__(256) void split_all(const float* __restrict__ x,
                                                 const float* __restrict__ w0,
                                                 const float* __restrict__ w1,
                                                 const float* __restrict__ w2,
                                                 const float* __restrict__ w3) {
    int i = blockIdx.x * 256 + threadIdx.x;
    const float* src;
    uint32_t *hp, *lp;
    int j;
    if (i < NX4) {
        src = x; j = i;
        hp = (uint32_t*)g_xhi; lp = (uint32_t*)g_xlo;
    } else {
        int t = i - NX4;
        int m = t / NW4;
        if (m >= 4) return;
        j = t - m * NW4;
        src = (m == 0) ? w0 : (m == 1) ? w1 : (m == 2) ? w2 : w3;
        hp = (uint32_t*)(g_whi[m]); lp = (uint32_t*)(g_wlo[m]);
    }
    float4 v = ((const float4*)src)[j];
    uint32_t h0, l0, h1, l1;
    hilo2(v.x, v.y, h0, l0);
    hilo2(v.z, v.w, h1, l1);
    hp[j * 2 + 0] = h0; hp[j * 2 + 1] = h1;
    lp[j * 2 + 0] = l0; lp[j * 2 + 1] = l1;
}

// ---------------------------------------------------------------------------
// Tensor GEMM: C[t,o] = sum_c X[t,c] * W[o,c], hi/lo split operands.
// CTA tile 128x64, 8 warps (each 16 rows x 64 cols). k-chunk 64,
// double-buffered cp.async, SINGLE sync per stage:
//   wait0 -> sync -> prefetch(next into retired buffer) -> commit -> compute
// ---------------------------------------------------------------------------
#define GS 72
#define GAL 18432
#define GBH 36864
#define GBL 46080
#define GSTG 55296
#define GEMM_SMEM 110592
#define NSTG (C_EMB / 64)     // 12

__global__ __launch_bounds__(256, 2) void gemm_tc(
    const bf16* __restrict__ Ahi, const bf16* __restrict__ Alo,
    const bf16* __restrict__ BhiB, const bf16* __restrict__ BloB,
    float* __restrict__ outf) {
    extern __shared__ bf16 smg[];
    const uint32_t sb = smem_u32(smg);
    const int tid = threadIdx.x, lane = tid & 31, wid = tid >> 5;
    const int row0 = blockIdx.x * 128;
    const int cy = blockIdx.y;            // 64-col tile == head for QKV
    const int col0 = cy * 64;
    const int z = blockIdx.z;
    const bf16* Bhi = BhiB + (size_t)z * C_EMB * C_EMB;
    const bf16* Blo = BloB + (size_t)z * C_EMB * C_EMB;
    const int g = lane >> 3, lr = lane & 7;

    float acc[8][4];
#pragma unroll
    for (int j = 0; j < 8; j++)
#pragma unroll
        for (int c = 0; c < 4; c++) acc[j][c] = 0.f;

    auto pf = [&](int s, uint32_t bo) {
        int k0 = s * 64;
#pragma unroll
        for (int itr = 0; itr < 4; itr++) {       // A: 128 rows
            int idx = tid + itr * 256;            // 0..1023
            int r = idx >> 3, q = idx & 7;
            uint32_t so = (uint32_t)((r * GS + q * 8) * 2);
            size_t ga = (size_t)(row0 + r) * C_EMB + k0 + q * 8;
            CP16(sb + bo + so,       Ahi + ga);
            CP16(sb + bo + GAL + so, Alo + ga);
        }
#pragma unroll
        for (int itr = 0; itr < 2; itr++) {       // B: 64 rows
            int idx = tid + itr * 256;            // 0..511
            int r = idx >> 3, q = idx & 7;
            uint32_t so = (uint32_t)((r * GS + q * 8) * 2);
            size_t gb = (size_t)(col0 + r) * C_EMB + k0 + q * 8;
            CP16(sb + bo + GBH + so, Bhi + gb);
            CP16(sb + bo + GBL + so, Blo + gb);
        }
    };

    pf(0, 0u);
    CPCOMMIT();

    for (int s = 0; s < NSTG; s++) {
        const uint32_t bo = (s & 1) ? (uint32_t)GSTG : 0u;
        CPWAIT0();          // stage s arrived (committed one iteration ago)
        __syncthreads();    // all warps done with the retired buffer + see s
        if (s + 1 < NSTG) {
            pf(s + 1, ((s + 1) & 1) ? (uint32_t)GSTG : 0u);  // retired buffer
            CPCOMMIT();
        }

#pragma unroll
        for (int kt = 0; kt < 4; kt++) {
            uint32_t ah[4], al[4];
            uint32_t aoff = (uint32_t)(((wid * 16 + lr + (g & 1) * 8) * GS +
                                        kt * 16 + (g >> 1) * 8) * 2);
            ldm4(sb + bo + aoff, ah);
            ldm4(sb + bo + GAL + aoff, al);
#pragma unroll
            for (int np = 0; np < 4; np++) {
                uint32_t boff = (uint32_t)(((np * 16 + lr + (g >> 1) * 8) * GS +
                                            kt * 16 + (g & 1) * 8) * 2);
                uint32_t bh[4], bl[4];
                ldm4(sb + bo + GBH + boff, bh);
                ldm4(sb + bo + GBL + boff, bl);
                mma16816(acc[2 * np],     ah, &bh[0]);
                mma16816(acc[2 * np + 1], ah, &bh[2]);
                mma16816(acc[2 * np],     ah, &bl[0]);
                mma16816(acc[2 * np + 1], ah, &bl[2]);
                mma16816(acc[2 * np],     al, &bh[0]);
                mma16816(acc[2 * np + 1], al, &bh[2]);
            }
        }
    }

    const int r = lane >> 2, cq = (lane & 3) * 2;
    const int grow = row0 + wid * 16 + r;
    bf16* Dhi = (z == 0) ? g_qhi : (z == 1) ? g_khi : g_vhi;
    bf16* Dlo = (z == 0) ? g_qlo : (z == 1) ? g_klo : g_vlo;
#pragma unroll
    for (int nt = 0; nt < 8; nt++) {
        int d = nt * 8 + cq;                       // 0..63 within col tile
        if (outf) {
            *(float2*)(outf + (size_t)grow * C_EMB + col0 + d) =
                make_float2(acc[nt][0], acc[nt][1]);
            *(float2*)(outf + (size_t)(grow + 8) * C_EMB + col0 + d) =
                make_float2(acc[nt][2], acc[nt][3]);
        } else {
            uint32_t h0, l0, h1, l1;
            hilo2(acc[nt][0], acc[nt][1], h0, l0);
            hilo2(acc[nt][2], acc[nt][3], h1, l1);
            size_t b0 = ((size_t)cy * T_SEQ + grow) * HD + d;
            size_t b1 = ((size_t)cy * T_SEQ + grow + 8) * HD + d;
            *(uint32_t*)(Dhi + b0) = h0;
            *(uint32_t*)(Dlo + b0) = l0;
            *(uint32_t*)(Dhi + b1) = h1;
            *(uint32_t*)(Dlo + b1) = l1;
        }
    }
}

// ---------------------------------------------------------------------------
// Tensor flash attention, causal. BLOCK_M=128 (8 warps x m16), BLOCK_N=64.
// Double-buffered cp.async KV pipeline, SINGLE sync per tile.
// PV uses full 3-term hi/lo split (ph*vh + ph*vl + pl*vh) — the residual
// term is load-bearing (dropping it measured 1.14e-3 rel err in R10).
// stage: KH=+0 KL=+9216 VH=+18432 VL=+27648 (36864 B); Q @73728/92160.
// ---------------------------------------------------------------------------
#define AS  72
#define STG 36864
#define AVHO 18432
#define AVLO 27648
#define AQH 73728
#define AQL 92160
#define ATTN_SMEM 110592

__global__ __launch_bounds__(256, 2) void attn_tc() {
    extern __shared__ char smc[];
    const uint32_t sb = smem_u32(smc);
    const int tid = threadIdx.x, lane = tid & 31, wid = tid >> 5;
    const int g = lane >> 3, lr = lane & 7;
    const int itc = gridDim.x - 1 - blockIdx.x;   // heavy first
    const int h = blockIdx.y;
    const int q0 = itc * 128;
    const int ntiles = 2 * itc + 2;               // KV tiles of 64

    const bf16* Qh = g_qhi + (size_t)h * T_SEQ * HD;
    const bf16* Ql = g_qlo + (size_t)h * T_SEQ * HD;
    const bf16* Kh = g_khi + (size_t)h * T_SEQ * HD;
    const bf16* Kl = g_klo + (size_t)h * T_SEQ * HD;
    const bf16* Vh = g_vhi + (size_t)h * T_SEQ * HD;
    const bf16* Vl = g_vlo + (size_t)h * T_SEQ * HD;

    // Q tile -> dedicated smem region (cp.async, first commit group)
#pragma unroll
    for (int itr = 0; itr < 4; itr++) {
        int idx = tid + itr * 256;
        int r = idx >> 3, q = idx & 7;
        uint32_t so = (uint32_t)((r * AS + q * 8) * 2);
        size_t gofs = (size_t)(q0 + r) * HD + q * 8;
        CP16(sb + AQH + so, Qh + gofs);
        CP16(sb + AQL + so, Ql + gofs);
    }

    auto prefetch = [&](int jt2, uint32_t bo) {
        int k0b = jt2 * 64;
#pragma unroll
        for (int itr = 0; itr < 2; itr++) {
            int idx = tid + itr * 256;
            int r = idx >> 3, q = idx & 7;
            uint32_t so = (uint32_t)((r * AS + q * 8) * 2);
            size_t gofs = (size_t)(k0b + r) * HD + q * 8;
            CP16(sb + bo + so,          Kh + gofs);
            CP16(sb + bo + 9216 + so,   Kl + gofs);
            CP16(sb + bo + AVHO + so,   Vh + gofs);
            CP16(sb + bo + AVLO + so,   Vl + gofs);
        }
    };

    float m[2] = {-INFINITY, -INFINITY}, lsum[2] = {0.f, 0.f};
    float ov[8][4];
#pragma unroll
    for (int i = 0; i < 8; i++)
#pragma unroll
        for (int c = 0; c < 4; c++) ov[i][c] = 0.f;

    prefetch(0, 0u);      // Q + stage0 in group 0
    CPCOMMIT();

    const uint32_t qoff_base = (uint32_t)(((wid * 16 + lr + (g & 1) * 8) * AS +
                                           (g >> 1) * 8) * 2);

    for (int jt = 0; jt < ntiles; jt++) {
        const uint32_t bo = (jt & 1) ? (uint32_t)STG : 0u;
        CPWAIT0();          // tile jt arrived (committed one iteration ago)
        __syncthreads();    // all warps done with retired buffer + see jt
        if (jt + 1 < ntiles) {
            prefetch(jt + 1, ((jt + 1) & 1) ? (uint32_t)STG : 0u);
            CPCOMMIT();
        }

        const int k0b = jt * 64;
        const bool skip = (wid * 16 + 15) < (k0b - q0);
        if (!skip) {
            // S = Q K^T  (Q frags re-loaded per k-step)
            float sv[8][4];
#pragma unroll
            for (int i = 0; i < 8; i++)
#pragma unroll
                for (int c = 0; c < 4; c++) sv[i][c] = 0.f;
#pragma unroll
            for (int kt = 0; kt < 4; kt++) {
                uint32_t qfh[4], qfl[4];
                uint32_t qa = qoff_base + (uint32_t)(kt * 32);
                ldm4(sb + AQH + qa, qfh);
                ldm4(sb + AQL + qa, qfl);
#pragma unroll
                for (int np = 0; np < 4; np++) {
                    uint32_t boff = (uint32_t)(((np * 16 + lr + (g >> 1) * 8) * AS +
                                                kt * 16 + (g & 1) * 8) * 2);
                    uint32_t bh[4], bl[4];
                    ldm4(sb + bo + boff, bh);
                    ldm4(sb + bo + 9216 + boff, bl);
                    mma16816(sv[2 * np],     qfh, &bh[0]);
                    mma16816(sv[2 * np + 1], qfh, &bh[2]);
                    mma16816(sv[2 * np],     qfh, &bl[0]);
                    mma16816(sv[2 * np + 1], qfh, &bl[2]);
                    mma16816(sv[2 * np],     qfl, &bh[0]);
                    mma16816(sv[2 * np + 1], qfl, &bh[2]);
                }
            }

            // scale into log2 domain + causal mask
            const float scl2 = 0.18033688f;   // 0.125 * log2(e)
            const int rbase = q0 + wid * 16 + (lane >> 2);
            const bool diag = (k0b + 63) > (q0 + wid * 16);
#pragma unroll
            for (int nt = 0; nt < 8; nt++) {
#pragma unroll
                for (int c = 0; c < 4; c++) {
                    float s = sv[nt][c] * scl2;
                    if (diag) {
                        int row = rbase + ((c >> 1) << 3);
                        int col = k0b + nt * 8 + (lane & 3) * 2 + (c & 1);
                        if (col > row) s = -INFINITY;
                    }
                    sv[nt][c] = s;
                }
            }
            // online softmax (exp2 domain)
#pragma unroll
            for (int half = 0; half < 2; half++) {
                int ci = half * 2;
                float mt = -INFINITY;
#pragma unroll
                for (int nt = 0; nt < 8; nt++)
                    mt = fmaxf(mt, fmaxf(sv[nt][ci], sv[nt][ci + 1]));
                mt = fmaxf(mt, __shfl_xor_sync(0xffffffffu, mt, 1));
                mt = fmaxf(mt, __shfl_xor_sync(0xffffffffu, mt, 2));
                float mn = fmaxf(m[half], mt);
                float corr = ex2(m[half] - mn);
                m[half] = mn;
                float rs = 0.f;
#pragma unroll
                for (int nt = 0; nt < 8; nt++) {
                    float p0 = ex2(sv[nt][ci] - mn);
                    float p1 = ex2(sv[nt][ci + 1] - mn);
                    sv[nt][ci] = p0; sv[nt][ci + 1] = p1;
                    rs += p0 + p1;
                }
                rs += __shfl_xor_sync(0xffffffffu, rs, 1);
                rs += __shfl_xor_sync(0xffffffffu, rs, 2);
                lsum[half] = lsum[half] * corr + rs;
#pragma unroll
                for (int dn = 0; dn < 8; dn++) {
                    ov[dn][ci] *= corr;
                    ov[dn][ci + 1] *= corr;
                }
            }

            // O += P V  (full hi/lo split: ph*vh + ph*vl + pl*vh)
#pragma unroll
            for (int kt = 0; kt < 4; kt++) {
                uint32_t pfh[4], pfl[4];
                hilo2(sv[2 * kt][0],     sv[2 * kt][1],     pfh[0], pfl[0]);
                hilo2(sv[2 * kt][2],     sv[2 * kt][3],     pfh[1], pfl[1]);
                hilo2(sv[2 * kt + 1][0], sv[2 * kt + 1][1], pfh[2], pfl[2]);
                hilo2(sv[2 * kt + 1][2], sv[2 * kt + 1][3], pfh[3], pfl[3]);
#pragma unroll
                for (int dp = 0; dp < 4; dp++) {
                    uint32_t vaddr = (uint32_t)(((kt * 16 + (lane & 15)) * AS +
                                                 dp * 16 + (lane >> 4) * 8) * 2);
                    uint32_t vfh[4], vfl[4];
                    ldm4t(sb + bo + AVHO + vaddr, vfh);
                    ldm4t(sb + bo + AVLO + vaddr, vfl);
                    mma16816(ov[2 * dp],     pfh, &vfh[0]);
                    mma16816(ov[2 * dp + 1], pfh, &vfh[2]);
                    mma16816(ov[2 * dp],     pfh, &vfl[0]);
                    mma16816(ov[2 * dp + 1], pfh, &vfl[2]);
                    mma16816(ov[2 * dp],     pfl, &vfh[0]);
                    mma16816(ov[2 * dp + 1], pfl, &vfh[2]);
                }
            }
        }
    }

    // epilogue: normalize, split hi/lo, write att [T, 768]
    const int r = lane >> 2, cq = (lane & 3) * 2;
#pragma unroll
    for (int half = 0; half < 2; half++) {
        float inv = 1.f / lsum[half];
        int rg = q0 + wid * 16 + r + half * 8;
#pragma unroll
        for (int dn = 0; dn < 8; dn++) {
            float v0 = ov[dn][half * 2] * inv;
            float v1 = ov[dn][half * 2 + 1] * inv;
            uint32_t hh, ll;
            hilo2(v0, v1, hh, ll);
            size_t base = (size_t)rg * C_EMB + h * HD + dn * 8 + cq;
            *(uint32_t*)(g_ahi + base) = hh;
            *(uint32_t*)(g_alo + base) = ll;
        }
    }
}

// ---------------------------------------------------------------------------
extern "C" void kernel_launch(void* const* d_in, const int* in_sizes, int n_in,
                              void* d_out, int out_size) {
    (void)in_sizes; (void)n_in; (void)out_size;
    const float* x  = (const float*)d_in[0];
    const float* wq = (const float*)d_in[1];
    const float* wk = (const float*)d_in[2];
    const float* wv = (const float*)d_in[3];
    const float* wo = (const float*)d_in[4];
    float* out = (float*)d_out;

    bf16 *xhi, *xlo, *whi, *wlo, *ahi, *alo;
    cudaGetSymbolAddress((void**)&xhi, g_xhi);
    cudaGetSymbolAddress((void**)&xlo, g_xlo);
    cudaGetSymbolAddress((void**)&whi, g_whi);
    cudaGetSymbolAddress((void**)&wlo, g_wlo);
    cudaGetSymbolAddress((void**)&ahi, g_ahi);
    cudaGetSymbolAddress((void**)&alo, g_alo);
    cudaFuncSetAttribute(gemm_tc, cudaFuncAttributeMaxDynamicSharedMemorySize,
                         GEMM_SMEM);
    cudaFuncSetAttribute(attn_tc, cudaFuncAttributeMaxDynamicSharedMemorySize,
                         ATTN_SMEM);
    const size_t WSZ = (size_t)C_EMB * C_EMB;

    int ntot = NX4 + 4 * NW4;
    split_all<<<(ntot + 255) / 256, 256>>>(x, wq, wk, wv, wo);

    dim3 ggrid(T_SEQ / 128, C_EMB / 64, 3);    // fused QKV: 1152 CTAs
    gemm_tc<<<ggrid, 256, GEMM_SMEM>>>(xhi, xlo, whi, wlo, nullptr);

    dim3 agrid(T_SEQ / 128, NH);               // 32 x 12
    attn_tc<<<agrid, 256, ATTN_SMEM>>>();

    dim3 ogrid(T_SEQ / 128, C_EMB / 64, 1);    // WO: 384 CTAs
    gemm_tc<<<ogrid, 256, GEMM_SMEM>>>(ahi, alo, whi + 3 * WSZ, wlo + 3 * WSZ, out);
}

// round 13
// speedup vs baseline: 1.0614x; 1.0199x over previous
#include <cuda_runtime.h>
#include <cuda_bf16.h>
#include <math.h>
#include <stdint.h>

#define T_SEQ 4096
#define C_EMB 768
#define NH    12
#define HD    64
#define NW4   147456          // (768*768)/4
#define NX4   786432          // (4096*768)/4

typedef __nv_bfloat16 bf16;
typedef __nv_bfloat162 bf162;

// ---------------------------------------------------------------------------
// Scratch (__device__ globals — allocation-guard-safe)
// ---------------------------------------------------------------------------
__device__ __align__(128) bf16 g_xhi[(size_t)T_SEQ * C_EMB];
__device__ __align__(128) bf16 g_xlo[(size_t)T_SEQ * C_EMB];
__device__ __align__(128) bf16 g_whi[4][(size_t)C_EMB * C_EMB];
__device__ __align__(128) bf16 g_wlo[4][(size_t)C_EMB * C_EMB];
__device__ __align__(128) bf16 g_qhi[(size_t)NH * T_SEQ * HD];
__device__ __align__(128) bf16 g_qlo[(size_t)NH * T_SEQ * HD];
__device__ __align__(128) bf16 g_khi[(size_t)NH * T_SEQ * HD];
__device__ __align__(128) bf16 g_klo[(size_t)NH * T_SEQ * HD];
__device__ __align__(128) bf16 g_vhi[(size_t)NH * T_SEQ * HD];
__device__ __align__(128) bf16 g_vlo[(size_t)NH * T_SEQ * HD];
__device__ __align__(128) bf16 g_ahi[(size_t)T_SEQ * C_EMB];
__device__ __align__(128) bf16 g_alo[(size_t)T_SEQ * C_EMB];
// split-KV partials: unnormalized O + (m, lsum) per row, 2 halves
__device__ __align__(128) float g_pO[2][NH][T_SEQ][HD];     // 25.2 MB
__device__ __align__(128) float g_pml[2][NH][T_SEQ][2];     // 786 KB

// ---------------------------------------------------------------------------
// Helpers (baseline PTX only — no 'a'-arch features)
// ---------------------------------------------------------------------------
__device__ __forceinline__ uint32_t smem_u32(const void* p) {
    uint32_t a;
    asm("{ .reg .u64 t; cvta.to.shared.u64 t, %1; cvt.u32.u64 %0, t; }"
        : "=r"(a) : "l"(p));
    return a;
}
__device__ __forceinline__ void ldm4(uint32_t addr, uint32_t* r) {
    asm volatile("ldmatrix.sync.aligned.m8n8.x4.shared.b16 {%0,%1,%2,%3}, [%4];"
                 : "=r"(r[0]), "=r"(r[1]), "=r"(r[2]), "=r"(r[3]) : "r"(addr));
}
__device__ __forceinline__ void ldm4t(uint32_t addr, uint32_t* r) {
    asm volatile("ldmatrix.sync.aligned.m8n8.x4.trans.shared.b16 {%0,%1,%2,%3}, [%4];"
                 : "=r"(r[0]), "=r"(r[1]), "=r"(r[2]), "=r"(r[3]) : "r"(addr));
}
__device__ __forceinline__ void mma16816(float* d, const uint32_t* a,
                                         const uint32_t* b) {
    asm volatile(
        "mma.sync.aligned.m16n8k16.row.col.f32.bf16.bf16.f32 "
        "{%0,%1,%2,%3}, {%4,%5,%6,%7}, {%8,%9}, {%0,%1,%2,%3};"
        : "+f"(d[0]), "+f"(d[1]), "+f"(d[2]), "+f"(d[3])
        : "r"(a[0]), "r"(a[1]), "r"(a[2]), "r"(a[3]), "r"(b[0]), "r"(b[1]));
}
__device__ __forceinline__ float ex2(float x) {
    float y;
    asm("ex2.approx.f32 %0, %1;" : "=f"(y) : "f"(x));
    return y;
}
__device__ __forceinline__ void hilo2(float v0, float v1, uint32_t& h, uint32_t& l) {
    bf162 hh, ll;
    hh.x = __float2bfloat16(v0); hh.y = __float2bfloat16(v1);
    ll.x = __float2bfloat16(v0 - __bfloat162float(hh.x));
    ll.y = __float2bfloat16(v1 - __bfloat162float(hh.y));
    h = *reinterpret_cast<uint32_t*>(&hh);
    l = *reinterpret_cast<uint32_t*>(&ll);
}
#define CP16(dst, src) \
    asm volatile("cp.async.cg.shared.global [%0], [%1], 16;" \
                 :: "r"(dst), "l"(src) : "memory")
#define CPCOMMIT() asm volatile("cp.async.commit_group;" ::: "memory")
#define CPWAIT0() asm volatile("cp.async.wait_group 0;" ::: "memory")

// ---------------------------------------------------------------------------
// fp32 -> bf16 (hi, lo) split: x and all 4 weights in one launch
// ---------------------------------------------------------------------------
__global__ __launch_bounds__(256) void split_all(const float* __restrict__ x,
                                                 const float* __restrict__ w0,
                                                 const float* __restrict__ w1,
                                                 const float* __restrict__ w2,
                                                 const float* __restrict__ w3) {
    int i = blockIdx.x * 256 + threadIdx.x;
    const float* src;
    uint32_t *hp, *lp;
    int j;
    if (i < NX4) {
        src = x; j = i;
        hp = (uint32_t*)g_xhi; lp = (uint32_t*)g_xlo;
    } else {
        int t = i - NX4;
        int m = t / NW4;
        if (m >= 4) return;
        j = t - m * NW4;
        src = (m == 0) ? w0 : (m == 1) ? w1 : (m == 2) ? w2 : w3;
        hp = (uint32_t*)(g_whi[m]); lp = (uint32_t*)(g_wlo[m]);
    }
    float4 v = ((const float4*)src)[j];
    uint32_t h0, l0, h1, l1;
    hilo2(v.x, v.y, h0, l0);
    hilo2(v.z, v.w, h1, l1);
    hp[j * 2 + 0] = h0; hp[j * 2 + 1] = h1;
    lp[j * 2 + 0] = l0; lp[j * 2 + 1] = l1;
}

// ---------------------------------------------------------------------------
// Tensor GEMM: C[t,o] = sum_c X[t,c] * W[o,c], hi/lo split operands.
// CTA tile 128x64, 8 warps. k-chunk 64, double-buffered cp.async,
// single sync per stage.
// ---------------------------------------------------------------------------
#define GS 72
#define GAL 18432
#define GBH 36864
#define GBL 46080
#define GSTG 55296
#define GEMM_SMEM 110592
#define NSTG (C_EMB / 64)     // 12

__global__ __launch_bounds__(256, 2) void gemm_tc(
    const bf16* __restrict__ Ahi, const bf16* __restrict__ Alo,
    const bf16* __restrict__ BhiB, const bf16* __restrict__ BloB,
    float* __restrict__ outf) {
    extern __shared__ bf16 smg[];
    const uint32_t sb = smem_u32(smg);
    const int tid = threadIdx.x, lane = tid & 31, wid = tid >> 5;
    const int row0 = blockIdx.x * 128;
    const int cy = blockIdx.y;            // 64-col tile == head for QKV
    const int col0 = cy * 64;
    const int z = blockIdx.z;
    const bf16* Bhi = BhiB + (size_t)z * C_EMB * C_EMB;
    const bf16* Blo = BloB + (size_t)z * C_EMB * C_EMB;
    const int g = lane >> 3, lr = lane & 7;

    float acc[8][4];
#pragma unroll
    for (int j = 0; j < 8; j++)
#pragma unroll
        for (int c = 0; c < 4; c++) acc[j][c] = 0.f;

    auto pf = [&](int s, uint32_t bo) {
        int k0 = s * 64;
#pragma unroll
        for (int itr = 0; itr < 4; itr++) {       // A: 128 rows
            int idx = tid + itr * 256;
            int r = idx >> 3, q = idx & 7;
            uint32_t so = (uint32_t)((r * GS + q * 8) * 2);
            size_t ga = (size_t)(row0 + r) * C_EMB + k0 + q * 8;
            CP16(sb + bo + so,       Ahi + ga);
            CP16(sb + bo + GAL + so, Alo + ga);
        }
#pragma unroll
        for (int itr = 0; itr < 2; itr++) {       // B: 64 rows
            int idx = tid + itr * 256;
            int r = idx >> 3, q = idx & 7;
            uint32_t so = (uint32_t)((r * GS + q * 8) * 2);
            size_t gb = (size_t)(col0 + r) * C_EMB + k0 + q * 8;
            CP16(sb + bo + GBH + so, Bhi + gb);
            CP16(sb + bo + GBL + so, Blo + gb);
        }
    };

    pf(0, 0u);
    CPCOMMIT();

    for (int s = 0; s < NSTG; s++) {
        const uint32_t bo = (s & 1) ? (uint32_t)GSTG : 0u;
        CPWAIT0();
        __syncthreads();
        if (s + 1 < NSTG) {
            pf(s + 1, ((s + 1) & 1) ? (uint32_t)GSTG : 0u);
            CPCOMMIT();
        }

#pragma unroll
        for (int kt = 0; kt < 4; kt++) {
            uint32_t ah[4], al[4];
            uint32_t aoff = (uint32_t)(((wid * 16 + lr + (g & 1) * 8) * GS +
                                        kt * 16 + (g >> 1) * 8) * 2);
            ldm4(sb + bo + aoff, ah);
            ldm4(sb + bo + GAL + aoff, al);
#pragma unroll
            for (int np = 0; np < 4; np++) {
                uint32_t boff = (uint32_t)(((np * 16 + lr + (g >> 1) * 8) * GS +
                                            kt * 16 + (g & 1) * 8) * 2);
                uint32_t bh[4], bl[4];
                ldm4(sb + bo + GBH + boff, bh);
                ldm4(sb + bo + GBL + boff, bl);
                mma16816(acc[2 * np],     ah, &bh[0]);
                mma16816(acc[2 * np + 1], ah, &bh[2]);
                mma16816(acc[2 * np],     ah, &bl[0]);
                mma16816(acc[2 * np + 1], ah, &bl[2]);
                mma16816(acc[2 * np],     al, &bh[0]);
                mma16816(acc[2 * np + 1], al, &bh[2]);
            }
        }
    }

    const int r = lane >> 2, cq = (lane & 3) * 2;
    const int grow = row0 + wid * 16 + r;
    bf16* Dhi = (z == 0) ? g_qhi : (z == 1) ? g_khi : g_vhi;
    bf16* Dlo = (z == 0) ? g_qlo : (z == 1) ? g_klo : g_vlo;
#pragma unroll
    for (int nt = 0; nt < 8; nt++) {
        int d = nt * 8 + cq;
        if (outf) {
            *(float2*)(outf + (size_t)grow * C_EMB + col0 + d) =
                make_float2(acc[nt][0], acc[nt][1]);
            *(float2*)(outf + (size_t)(grow + 8) * C_EMB + col0 + d) =
                make_float2(acc[nt][2], acc[nt][3]);
        } else {
            uint32_t h0, l0, h1, l1;
            hilo2(acc[nt][0], acc[nt][1], h0, l0);
            hilo2(acc[nt][2], acc[nt][3], h1, l1);
            size_t b0 = ((size_t)cy * T_SEQ + grow) * HD + d;
            size_t b1 = ((size_t)cy * T_SEQ + grow + 8) * HD + d;
            *(uint32_t*)(Dhi + b0) = h0;
            *(uint32_t*)(Dlo + b0) = l0;
            *(uint32_t*)(Dhi + b1) = h1;
            *(uint32_t*)(Dlo + b1) = l1;
        }
    }
}

// ---------------------------------------------------------------------------
// Split-KV tensor flash attention, causal. BLOCK_M=128, BLOCK_N=64.
// Grid (32, NH, 2): z-th CTA handles KV tiles jt = z, z+2, ... (strided),
// so each (q-tile, head) splits its triangular work in two balanced halves
// (max job 32 tiles vs 66 unsplit). Partial unnormalized O + (m, l) written
// to scratch; combine kernel merges.
// stage: KH=+0 KL=+9216 VH=+18432 VL=+27648 (36864 B); Q @73728/92160.
// ---------------------------------------------------------------------------
#define AS  72
#define STG 36864
#define AVHO 18432
#define AVLO 27648
#define AQH 73728
#define AQL 92160
#define ATTN_SMEM 110592

__global__ __launch_bounds__(256, 2) void attn_tc() {
    extern __shared__ char smc[];
    const uint32_t sb = smem_u32(smc);
    const int tid = threadIdx.x, lane = tid & 31, wid = tid >> 5;
    const int g = lane >> 3, lr = lane & 7;
    const int itc = gridDim.x - 1 - blockIdx.x;   // heavy first
    const int h = blockIdx.y;
    const int z = blockIdx.z;                     // KV split half
    const int q0 = itc * 128;
    const int cnt = itc + 1;                      // tiles in this half

    const bf16* Qh = g_qhi + (size_t)h * T_SEQ * HD;
    const bf16* Ql = g_qlo + (size_t)h * T_SEQ * HD;
    const bf16* Kh = g_khi + (size_t)h * T_SEQ * HD;
    const bf16* Kl = g_klo + (size_t)h * T_SEQ * HD;
    const bf16* Vh = g_vhi + (size_t)h * T_SEQ * HD;
    const bf16* Vl = g_vlo + (size_t)h * T_SEQ * HD;

    // Q tile -> dedicated smem region (cp.async, first commit group)
#pragma unroll
    for (int itr = 0; itr < 4; itr++) {
        int idx = tid + itr * 256;
        int r = idx >> 3, q = idx & 7;
        uint32_t so = (uint32_t)((r * AS + q * 8) * 2);
        size_t gofs = (size_t)(q0 + r) * HD + q * 8;
        CP16(sb + AQH + so, Qh + gofs);
        CP16(sb + AQL + so, Ql + gofs);
    }

    auto prefetch = [&](int jt2, uint32_t bo) {
        int k0b = jt2 * 64;
#pragma unroll
        for (int itr = 0; itr < 2; itr++) {
            int idx = tid + itr * 256;
            int r = idx >> 3, q = idx & 7;
            uint32_t so = (uint32_t)((r * AS + q * 8) * 2);
            size_t gofs = (size_t)(k0b + r) * HD + q * 8;
            CP16(sb + bo + so,          Kh + gofs);
            CP16(sb + bo + 9216 + so,   Kl + gofs);
            CP16(sb + bo + AVHO + so,   Vh + gofs);
            CP16(sb + bo + AVLO + so,   Vl + gofs);
        }
    };

    float m[2] = {-INFINITY, -INFINITY}, lsum[2] = {0.f, 0.f};
    float ov[8][4];
#pragma unroll
    for (int i = 0; i < 8; i++)
#pragma unroll
        for (int c = 0; c < 4; c++) ov[i][c] = 0.f;

    prefetch(z, 0u);      // Q + first tile in group 0
    CPCOMMIT();

    const uint32_t qoff_base = (uint32_t)(((wid * 16 + lr + (g & 1) * 8) * AS +
                                           (g >> 1) * 8) * 2);

    for (int lt = 0; lt < cnt; lt++) {
        const int jt = z + 2 * lt;
        const uint32_t bo = (lt & 1) ? (uint32_t)STG : 0u;
        CPWAIT0();
        __syncthreads();
        if (lt + 1 < cnt) {
            prefetch(z + 2 * (lt + 1), ((lt + 1) & 1) ? (uint32_t)STG : 0u);
            CPCOMMIT();
        }

        const int k0b = jt * 64;
        const bool skip = (wid * 16 + 15) < (k0b - q0);
        if (!skip) {
            // S = Q K^T  (Q frags re-loaded per k-step)
            float sv[8][4];
#pragma unroll
            for (int i = 0; i < 8; i++)
#pragma unroll
                for (int c = 0; c < 4; c++) sv[i][c] = 0.f;
#pragma unroll
            for (int kt = 0; kt < 4; kt++) {
                uint32_t qfh[4], qfl[4];
                uint32_t qa = qoff_base + (uint32_t)(kt * 32);
                ldm4(sb + AQH + qa, qfh);
                ldm4(sb + AQL + qa, qfl);
#pragma unroll
                for (int np = 0; np < 4; np++) {
                    uint32_t boff = (uint32_t)(((np * 16 + lr + (g >> 1) * 8) * AS +
                                                kt * 16 + (g & 1) * 8) * 2);
                    uint32_t bh[4], bl[4];
                    ldm4(sb + bo + boff, bh);
                    ldm4(sb + bo + 9216 + boff, bl);
                    mma16816(sv[2 * np],     qfh, &bh[0]);
                    mma16816(sv[2 * np + 1], qfh, &bh[2]);
                    mma16816(sv[2 * np],     qfh, &bl[0]);
                    mma16816(sv[2 * np + 1], qfh, &bl[2]);
                    mma16816(sv[2 * np],     qfl, &bh[0]);
                    mma16816(sv[2 * np + 1], qfl, &bh[2]);
                }
            }

            // scale into log2 domain + causal mask
            const float scl2 = 0.18033688f;   // 0.125 * log2(e)
            const int rbase = q0 + wid * 16 + (lane >> 2);
            const bool diag = (k0b + 63) > (q0 + wid * 16);
#pragma unroll
            for (int nt = 0; nt < 8; nt++) {
#pragma unroll
                for (int c = 0; c < 4; c++) {
                    float s = sv[nt][c] * scl2;
                    if (diag) {
                        int row = rbase + ((c >> 1) << 3);
                        int col = k0b + nt * 8 + (lane & 3) * 2 + (c & 1);
                        if (col > row) s = -INFINITY;
                    }
                    sv[nt][c] = s;
                }
            }
            // online softmax (exp2 domain)
#pragma unroll
            for (int half = 0; half < 2; half++) {
                int ci = half * 2;
                float mt = -INFINITY;
#pragma unroll
                for (int nt = 0; nt < 8; nt++)
                    mt = fmaxf(mt, fmaxf(sv[nt][ci], sv[nt][ci + 1]));
                mt = fmaxf(mt, __shfl_xor_sync(0xffffffffu, mt, 1));
                mt = fmaxf(mt, __shfl_xor_sync(0xffffffffu, mt, 2));
                float mn = fmaxf(m[half], mt);
                float corr = ex2(m[half] - mn);
                m[half] = mn;
                float rs = 0.f;
#pragma unroll
                for (int nt = 0; nt < 8; nt++) {
                    float p0 = ex2(sv[nt][ci] - mn);
                    float p1 = ex2(sv[nt][ci + 1] - mn);
                    sv[nt][ci] = p0; sv[nt][ci + 1] = p1;
                    rs += p0 + p1;
                }
                rs += __shfl_xor_sync(0xffffffffu, rs, 1);
                rs += __shfl_xor_sync(0xffffffffu, rs, 2);
                lsum[half] = lsum[half] * corr + rs;
#pragma unroll
                for (int dn = 0; dn < 8; dn++) {
                    ov[dn][ci] *= corr;
                    ov[dn][ci + 1] *= corr;
                }
            }

            // O += P V  (full hi/lo split: ph*vh + ph*vl + pl*vh)
#pragma unroll
            for (int kt = 0; kt < 4; kt++) {
                uint32_t pfh[4], pfl[4];
                hilo2(sv[2 * kt][0],     sv[2 * kt][1],     pfh[0], pfl[0]);
                hilo2(sv[2 * kt][2],     sv[2 * kt][3],     pfh[1], pfl[1]);
                hilo2(sv[2 * kt + 1][0], sv[2 * kt + 1][1], pfh[2], pfl[2]);
                hilo2(sv[2 * kt + 1][2], sv[2 * kt + 1][3], pfh[3], pfl[3]);
#pragma unroll
                for (int dp = 0; dp < 4; dp++) {
                    uint32_t vaddr = (uint32_t)(((kt * 16 + (lane & 15)) * AS +
                                                 dp * 16 + (lane >> 4) * 8) * 2);
                    uint32_t vfh[4], vfl[4];
                    ldm4t(sb + bo + AVHO + vaddr, vfh);
                    ldm4t(sb + bo + AVLO + vaddr, vfl);
                    mma16816(ov[2 * dp],     pfh, &vfh[0]);
                    mma16816(ov[2 * dp + 1], pfh, &vfh[2]);
                    mma16816(ov[2 * dp],     pfh, &vfl[0]);
                    mma16816(ov[2 * dp + 1], pfh, &vfl[2]);
                    mma16816(ov[2 * dp],     pfl, &vfh[0]);
                    mma16816(ov[2 * dp + 1], pfl, &vfh[2]);
                }
            }
        }
    }

    // epilogue: write UNNORMALIZED partial O + (m, lsum) for this half
    const int r = lane >> 2, cq = (lane & 3) * 2;
#pragma unroll
    for (int half = 0; half < 2; half++) {
        int rg = q0 + wid * 16 + r + half * 8;
        g_pml[z][h][rg][0] = m[half];       // quad-redundant, same value
        g_pml[z][h][rg][1] = lsum[half];
#pragma unroll
        for (int dn = 0; dn < 8; dn++) {
            *(float2*)&g_pO[z][h][rg][dn * 8 + cq] =
                make_float2(ov[dn][half * 2], ov[dn][half * 2 + 1]);
        }
    }
}

// ---------------------------------------------------------------------------
// Combine the two KV halves:  O = (w0*O0 + w1*O1) / (w0*l0 + w1*l1),
// w_z = 2^(m_z - max(m0, m1)).  Writes bf16 hi/lo att [T, 768].
// One thread per 2 output columns.
// ---------------------------------------------------------------------------
__global__ __launch_bounds__(256) void combine_kv() {
    int idx = blockIdx.x * 256 + threadIdx.x;     // over NH*T_SEQ*32
    int h = idx / (T_SEQ * 32);
    int rem = idx - h * (T_SEQ * 32);
    int row = rem >> 5;
    int c2 = (rem & 31) * 2;
    float m0 = g_pml[0][h][row][0], l0 = g_pml[0][h][row][1];
    float m1 = g_pml[1][h][row][0], l1 = g_pml[1][h][row][1];
    float mm = fmaxf(m0, m1);
    float w0 = ex2(m0 - mm), w1 = ex2(m1 - mm);
    float inv = 1.f / (l0 * w0 + l1 * w1);
    float2 o0 = *(float2*)&g_pO[0][h][row][c2];
    float2 o1 = *(float2*)&g_pO[1][h][row][c2];
    float v0 = (o0.x * w0 + o1.x * w1) * inv;
    float v1 = (o0.y * w0 + o1.y * w1) * inv;
    uint32_t hh, ll;
    hilo2(v0, v1, hh, ll);
    size_t base = (size_t)row * C_EMB + h * HD + c2;
    *(uint32_t*)(g_ahi + base) = hh;
    *(uint32_t*)(g_alo + base) = ll;
}

// ---------------------------------------------------------------------------
extern "C" void kernel_launch(void* const* d_in, const int* in_sizes, int n_in,
                              void* d_out, int out_size) {
    (void)in_sizes; (void)n_in; (void)out_size;
    const float* x  = (const float*)d_in[0];
    const float* wq = (const float*)d_in[1];
    const float* wk = (const float*)d_in[2];
    const float* wv = (const float*)d_in[3];
    const float* wo = (const float*)d_in[4];
    float* out = (float*)d_out;

    bf16 *xhi, *xlo, *whi, *wlo, *ahi, *alo;
    cudaGetSymbolAddress((void**)&xhi, g_xhi);
    cudaGetSymbolAddress((void**)&xlo, g_xlo);
    cudaGetSymbolAddress((void**)&whi, g_whi);
    cudaGetSymbolAddress((void**)&wlo, g_wlo);
    cudaGetSymbolAddress((void**)&ahi, g_ahi);
    cudaGetSymbolAddress((void**)&alo, g_alo);
    cudaFuncSetAttribute(gemm_tc, cudaFuncAttributeMaxDynamicSharedMemorySize,
                         GEMM_SMEM);
    cudaFuncSetAttribute(attn_tc, cudaFuncAttributeMaxDynamicSharedMemorySize,
                         ATTN_SMEM);
    const size_t WSZ = (size_t)C_EMB * C_EMB;

    int ntot = NX4 + 4 * NW4;
    split_all<<<(ntot + 255) / 256, 256>>>(x, wq, wk, wv, wo);

    dim3 ggrid(T_SEQ / 128, C_EMB / 64, 3);    // fused QKV: 1152 CTAs
    gemm_tc<<<ggrid, 256, GEMM_SMEM>>>(xhi, xlo, whi, wlo, nullptr);

    dim3 agrid(T_SEQ / 128, NH, 2);            // split-KV: 768 CTAs
    attn_tc<<<agrid, 256, ATTN_SMEM>>>();

    combine_kv<<<(NH * T_SEQ * 32) / 256, 256>>>();

    dim3 ogrid(T_SEQ / 128, C_EMB / 64, 1);    // WO: 384 CTAs
    gemm_tc<<<ogrid, 256, GEMM_SMEM>>>(ahi, alo, whi + 3 * WSZ, wlo + 3 * WSZ, out);
}

// round 15
// speedup vs baseline: 1.0708x; 1.0089x over previous
#include <cuda_runtime.h>
#include <cuda_bf16.h>
#include <math.h>
#include <stdint.h>

#define T_SEQ 4096
#define C_EMB 768
#define NH    12
#define HD    64
#define NW4   147456          // (768*768)/4
#define NX4   786432          // (4096*768)/4

typedef __nv_bfloat16 bf16;
typedef __nv_bfloat162 bf162;

// ---------------------------------------------------------------------------
// Scratch (__device__ globals — allocation-guard-safe)
// ---------------------------------------------------------------------------
__device__ __align__(128) bf16 g_xhi[(size_t)T_SEQ * C_EMB];
__device__ __align__(128) bf16 g_xlo[(size_t)T_SEQ * C_EMB];
__device__ __align__(128) bf16 g_whi[4][(size_t)C_EMB * C_EMB];
__device__ __align__(128) bf16 g_wlo[4][(size_t)C_EMB * C_EMB];
__device__ __align__(128) bf16 g_qhi[(size_t)NH * T_SEQ * HD];
__device__ __align__(128) bf16 g_qlo[(size_t)NH * T_SEQ * HD];
__device__ __align__(128) bf16 g_khi[(size_t)NH * T_SEQ * HD];
__device__ __align__(128) bf16 g_klo[(size_t)NH * T_SEQ * HD];
__device__ __align__(128) bf16 g_vhi[(size_t)NH * T_SEQ * HD];
__device__ __align__(128) bf16 g_vlo[(size_t)NH * T_SEQ * HD];
__device__ __align__(128) bf16 g_ahi[(size_t)T_SEQ * C_EMB];
__device__ __align__(128) bf16 g_alo[(size_t)T_SEQ * C_EMB];
// split-KV partials: unnormalized O + (m, lsum) per row, 2 halves
__device__ __align__(128) float g_pO[2][NH][T_SEQ][HD];     // 25.2 MB
__device__ __align__(128) float g_pml[2][NH][T_SEQ][2];     // 786 KB

// ---------------------------------------------------------------------------
// Helpers (baseline PTX only — no 'a'-arch features)
// ---------------------------------------------------------------------------
__device__ __forceinline__ uint32_t smem_u32(const void* p) {
    uint32_t a;
    asm("{ .reg .u64 t; cvta.to.shared.u64 t, %1; cvt.u32.u64 %0, t; }"
        : "=r"(a) : "l"(p));
    return a;
}
__device__ __forceinline__ void ldm4(uint32_t addr, uint32_t* r) {
    asm volatile("ldmatrix.sync.aligned.m8n8.x4.shared.b16 {%0,%1,%2,%3}, [%4];"
                 : "=r"(r[0]), "=r"(r[1]), "=r"(r[2]), "=r"(r[3]) : "r"(addr));
}
__device__ __forceinline__ void ldm4t(uint32_t addr, uint32_t* r) {
    asm volatile("ldmatrix.sync.aligned.m8n8.x4.trans.shared.b16 {%0,%1,%2,%3}, [%4];"
                 : "=r"(r[0]), "=r"(r[1]), "=r"(r[2]), "=r"(r[3]) : "r"(addr));
}
__device__ __forceinline__ void mma16816(float* d, const uint32_t* a,
                                         const uint32_t* b) {
    asm volatile(
        "mma.sync.aligned.m16n8k16.row.col.f32.bf16.bf16.f32 "
        "{%0,%1,%2,%3}, {%4,%5,%6,%7}, {%8,%9}, {%0,%1,%2,%3};"
        : "+f"(d[0]), "+f"(d[1]), "+f"(d[2]), "+f"(d[3])
        : "r"(a[0]), "r"(a[1]), "r"(a[2]), "r"(a[3]), "r"(b[0]), "r"(b[1]));
}
__device__ __forceinline__ float ex2(float x) {
    float y;
    asm("ex2.approx.f32 %0, %1;" : "=f"(y) : "f"(x));
    return y;
}
__device__ __forceinline__ void hilo2(float v0, float v1, uint32_t& h, uint32_t& l) {
    bf162 hh, ll;
    hh.x = __float2bfloat16(v0); hh.y = __float2bfloat16(v1);
    ll.x = __float2bfloat16(v0 - __bfloat162float(hh.x));
    ll.y = __float2bfloat16(v1 - __bfloat162float(hh.y));
    h = *reinterpret_cast<uint32_t*>(&hh);
    l = *reinterpret_cast<uint32_t*>(&ll);
}
#define CP16(dst, src) \
    asm volatile("cp.async.cg.shared.global [%0], [%1], 16;" \
                 :: "r"(dst), "l"(src) : "memory")
#define CPCOMMIT() asm volatile("cp.async.commit_group;" ::: "memory")
#define CPWAIT0() asm volatile("cp.async.wait_group 0;" ::: "memory")

// ---------------------------------------------------------------------------
// fp32 -> bf16 (hi, lo) split: x and all 4 weights in one launch
// ---------------------------------------------------------------------------
__global__ __launch_bounds__(256) void split_all(const float* __restrict__ x,
                                                 const float* __restrict__ w0,
                                                 const float* __restrict__ w1,
                                                 const float* __restrict__ w2,
                                                 const float* __restrict__ w3) {
    int i = blockIdx.x * 256 + threadIdx.x;
    const float* src;
    uint32_t *hp, *lp;
    int j;
    if (i < NX4) {
        src = x; j = i;
        hp = (uint32_t*)g_xhi; lp = (uint32_t*)g_xlo;
    } else {
        int t = i - NX4;
        int m = t / NW4;
        if (m >= 4) return;
        j = t - m * NW4;
        src = (m == 0) ? w0 : (m == 1) ? w1 : (m == 2) ? w2 : w3;
        hp = (uint32_t*)(g_whi[m]); lp = (uint32_t*)(g_wlo[m]);
    }
    float4 v = ((const float4*)src)[j];
    uint32_t h0, l0, h1, l1;
    hilo2(v.x, v.y, h0, l0);
    hilo2(v.z, v.w, h1, l1);
    hp[j * 2 + 0] = h0; hp[j * 2 + 1] = h1;
    lp[j * 2 + 0] = l0; lp[j * 2 + 1] = l1;
}

// ---------------------------------------------------------------------------
// Tensor GEMM: C[t,o] = sum_c X[t,c] * W[o,c], hi/lo split operands.
// CTA tile 128x64, 8 warps. k-chunk 64, double-buffered cp.async,
// single sync per stage. Inner loop: 3 passes per k-step, each rotating
// through all 8 accumulators (dep distance 8 -> no MMA-latency stalls).
// ---------------------------------------------------------------------------
#define GS 72
#define GAL 18432
#define GBH 36864
#define GBL 46080
#define GSTG 55296
#define GEMM_SMEM 110592
#define NSTG (C_EMB / 64)     // 12

__global__ __launch_bounds__(256, 2) void gemm_tc(
    const bf16* __restrict__ Ahi, const bf16* __restrict__ Alo,
    const bf16* __restrict__ BhiB, const bf16* __restrict__ BloB,
    float* __restrict__ outf) {
    extern __shared__ bf16 smg[];
    const uint32_t sb = smem_u32(smg);
    const int tid = threadIdx.x, lane = tid & 31, wid = tid >> 5;
    const int row0 = blockIdx.x * 128;
    const int cy = blockIdx.y;            // 64-col tile == head for QKV
    const int col0 = cy * 64;
    const int z = blockIdx.z;
    const bf16* Bhi = BhiB + (size_t)z * C_EMB * C_EMB;
    const bf16* Blo = BloB + (size_t)z * C_EMB * C_EMB;
    const int g = lane >> 3, lr = lane & 7;

    float acc[8][4];
#pragma unroll
    for (int j = 0; j < 8; j++)
#pragma unroll
        for (int c = 0; c < 4; c++) acc[j][c] = 0.f;

    auto pf = [&](int s, uint32_t bo) {
        int k0 = s * 64;
#pragma unroll
        for (int itr = 0; itr < 4; itr++) {       // A: 128 rows
            int idx = tid + itr * 256;
            int r = idx >> 3, q = idx & 7;
            uint32_t so = (uint32_t)((r * GS + q * 8) * 2);
            size_t ga = (size_t)(row0 + r) * C_EMB + k0 + q * 8;
            CP16(sb + bo + so,       Ahi + ga);
            CP16(sb + bo + GAL + so, Alo + ga);
        }
#pragma unroll
        for (int itr = 0; itr < 2; itr++) {       // B: 64 rows
            int idx = tid + itr * 256;
            int r = idx >> 3, q = idx & 7;
            uint32_t so = (uint32_t)((r * GS + q * 8) * 2);
            size_t gb = (size_t)(col0 + r) * C_EMB + k0 + q * 8;
            CP16(sb + bo + GBH + so, Bhi + gb);
            CP16(sb + bo + GBL + so, Blo + gb);
        }
    };

    pf(0, 0u);
    CPCOMMIT();

    for (int s = 0; s < NSTG; s++) {
        const uint32_t bo = (s & 1) ? (uint32_t)GSTG : 0u;
        CPWAIT0();
        __syncthreads();
        if (s + 1 < NSTG) {
            pf(s + 1, ((s + 1) & 1) ? (uint32_t)GSTG : 0u);
            CPCOMMIT();
        }

#pragma unroll
        for (int kt = 0; kt < 4; kt++) {
            uint32_t ah[4], al[4];
            uint32_t aoff = (uint32_t)(((wid * 16 + lr + (g & 1) * 8) * GS +
                                        kt * 16 + (g >> 1) * 8) * 2);
            ldm4(sb + bo + aoff, ah);
            ldm4(sb + bo + GAL + aoff, al);
            // pass 1: ah * bh  (8 accumulators rotate -> dep distance 8)
#pragma unroll
            for (int np = 0; np < 4; np++) {
                uint32_t boff = (uint32_t)(((np * 16 + lr + (g >> 1) * 8) * GS +
                                            kt * 16 + (g & 1) * 8) * 2);
                uint32_t bf[4];
                ldm4(sb + bo + GBH + boff, bf);
                mma16816(acc[2 * np],     ah, &bf[0]);
                mma16816(acc[2 * np + 1], ah, &bf[2]);
            }
            // pass 2: ah * bl
#pragma unroll
            for (int np = 0; np < 4; np++) {
                uint32_t boff = (uint32_t)(((np * 16 + lr + (g >> 1) * 8) * GS +
                                            kt * 16 + (g & 1) * 8) * 2);
                uint32_t bf[4];
                ldm4(sb + bo + GBL + boff, bf);
                mma16816(acc[2 * np],     ah, &bf[0]);
                mma16816(acc[2 * np + 1], ah, &bf[2]);
            }
            // pass 3: al * bh
#pragma unroll
            for (int np = 0; np < 4; np++) {
                uint32_t boff = (uint32_t)(((np * 16 + lr + (g >> 1) * 8) * GS +
                                            kt * 16 + (g & 1) * 8) * 2);
                uint32_t bf[4];
                ldm4(sb + bo + GBH + boff, bf);
                mma16816(acc[2 * np],     al, &bf[0]);
                mma16816(acc[2 * np + 1], al, &bf[2]);
            }
        }
    }

    const int r = lane >> 2, cq = (lane & 3) * 2;
    const int grow = row0 + wid * 16 + r;
    bf16* Dhi = (z == 0) ? g_qhi : (z == 1) ? g_khi : g_vhi;
    bf16* Dlo = (z == 0) ? g_qlo : (z == 1) ? g_klo : g_vlo;
#pragma unroll
    for (int nt = 0; nt < 8; nt++) {
        int d = nt * 8 + cq;
        if (outf) {
            *(float2*)(outf + (size_t)grow * C_EMB + col0 + d) =
                make_float2(acc[nt][0], acc[nt][1]);
            *(float2*)(outf + (size_t)(grow + 8) * C_EMB + col0 + d) =
                make_float2(acc[nt][2], acc[nt][3]);
        } else {
            uint32_t h0, l0, h1, l1;
            hilo2(acc[nt][0], acc[nt][1], h0, l0);
            hilo2(acc[nt][2], acc[nt][3], h1, l1);
            size_t b0 = ((size_t)cy * T_SEQ + grow) * HD + d;
            size_t b1 = ((size_t)cy * T_SEQ + grow + 8) * HD + d;
            *(uint32_t*)(Dhi + b0) = h0;
            *(uint32_t*)(Dlo + b0) = l0;
            *(uint32_t*)(Dhi + b1) = h1;
            *(uint32_t*)(Dlo + b1) = l1;
        }
    }
}

// ---------------------------------------------------------------------------
// Split-KV tensor flash attention, causal. BLOCK_M=128, BLOCK_N=64.
// Grid (32, NH, 2): z-th CTA handles KV tiles jt = z, z+2, ... (strided).
// S and PV loops restructured into per-term passes (dep distance 8).
// stage: KH=+0 KL=+9216 VH=+18432 VL=+27648 (36864 B); Q @73728/92160.
// ---------------------------------------------------------------------------
#define AS  72
#define STG 36864
#define AVHO 18432
#define AVLO 27648
#define AQH 73728
#define AQL 92160
#define ATTN_SMEM 110592

__global__ __launch_bounds__(256, 2) void attn_tc() {
    extern __shared__ char smc[];
    const uint32_t sb = smem_u32(smc);
    const int tid = threadIdx.x, lane = tid & 31, wid = tid >> 5;
    const int g = lane >> 3, lr = lane & 7;
    const int itc = gridDim.x - 1 - blockIdx.x;   // heavy first
    const int h = blockIdx.y;
    const int z = blockIdx.z;                     // KV split half
    const int q0 = itc * 128;
    const int cnt = itc + 1;                      // tiles in this half

    const bf16* Qh = g_qhi + (size_t)h * T_SEQ * HD;
    const bf16* Ql = g_qlo + (size_t)h * T_SEQ * HD;
    const bf16* Kh = g_khi + (size_t)h * T_SEQ * HD;
    const bf16* Kl = g_klo + (size_t)h * T_SEQ * HD;
    const bf16* Vh = g_vhi + (size_t)h * T_SEQ * HD;
    const bf16* Vl = g_vlo + (size_t)h * T_SEQ * HD;

    // Q tile -> dedicated smem region (cp.async, first commit group)
#pragma unroll
    for (int itr = 0; itr < 4; itr++) {
        int idx = tid + itr * 256;
        int r = idx >> 3, q = idx & 7;
        uint32_t so = (uint32_t)((r * AS + q * 8) * 2);
        size_t gofs = (size_t)(q0 + r) * HD + q * 8;
        CP16(sb + AQH + so, Qh + gofs);
        CP16(sb + AQL + so, Ql + gofs);
    }

    auto prefetch = [&](int jt2, uint32_t bo) {
        int k0b = jt2 * 64;
#pragma unroll
        for (int itr = 0; itr < 2; itr++) {
            int idx = tid + itr * 256;
            int r = idx >> 3, q = idx & 7;
            uint32_t so = (uint32_t)((r * AS + q * 8) * 2);
            size_t gofs = (size_t)(k0b + r) * HD + q * 8;
            CP16(sb + bo + so,          Kh + gofs);
            CP16(sb + bo + 9216 + so,   Kl + gofs);
            CP16(sb + bo + AVHO + so,   Vh + gofs);
            CP16(sb + bo + AVLO + so,   Vl + gofs);
        }
    };

    float m[2] = {-INFINITY, -INFINITY}, lsum[2] = {0.f, 0.f};
    float ov[8][4];
#pragma unroll
    for (int i = 0; i < 8; i++)
#pragma unroll
        for (int c = 0; c < 4; c++) ov[i][c] = 0.f;

    prefetch(z, 0u);      // Q + first tile in group 0
    CPCOMMIT();

    const uint32_t qoff_base = (uint32_t)(((wid * 16 + lr + (g & 1) * 8) * AS +
                                           (g >> 1) * 8) * 2);

    for (int lt = 0; lt < cnt; lt++) {
        const int jt = z + 2 * lt;
        const uint32_t bo = (lt & 1) ? (uint32_t)STG : 0u;
        CPWAIT0();
        __syncthreads();
        if (lt + 1 < cnt) {
            prefetch(z + 2 * (lt + 1), ((lt + 1) & 1) ? (uint32_t)STG : 0u);
            CPCOMMIT();
        }

        const int k0b = jt * 64;
        const bool skip = (wid * 16 + 15) < (k0b - q0);
        if (!skip) {
            // S = Q K^T : per k-step, 3 passes (qh*kh, qh*kl, ql*kh)
            float sv[8][4];
#pragma unroll
            for (int i = 0; i < 8; i++)
#pragma unroll
                for (int c = 0; c < 4; c++) sv[i][c] = 0.f;
#pragma unroll
            for (int kt = 0; kt < 4; kt++) {
                uint32_t qfh[4], qfl[4];
                uint32_t qa = qoff_base + (uint32_t)(kt * 32);
                ldm4(sb + AQH + qa, qfh);
                ldm4(sb + AQL + qa, qfl);
#pragma unroll
                for (int np = 0; np < 4; np++) {
                    uint32_t boff = (uint32_t)(((np * 16 + lr + (g >> 1) * 8) * AS +
                                                kt * 16 + (g & 1) * 8) * 2);
                    uint32_t bf[4];
                    ldm4(sb + bo + boff, bf);
                    mma16816(sv[2 * np],     qfh, &bf[0]);
                    mma16816(sv[2 * np + 1], qfh, &bf[2]);
                }
#pragma unroll
                for (int np = 0; np < 4; np++) {
                    uint32_t boff = (uint32_t)(((np * 16 + lr + (g >> 1) * 8) * AS +
                                                kt * 16 + (g & 1) * 8) * 2);
                    uint32_t bf[4];
                    ldm4(sb + bo + 9216 + boff, bf);
                    mma16816(sv[2 * np],     qfh, &bf[0]);
                    mma16816(sv[2 * np + 1], qfh, &bf[2]);
                }
#pragma unroll
                for (int np = 0; np < 4; np++) {
                    uint32_t boff = (uint32_t)(((np * 16 + lr + (g >> 1) * 8) * AS +
                                                kt * 16 + (g & 1) * 8) * 2);
                    uint32_t bf[4];
                    ldm4(sb + bo + boff, bf);
                    mma16816(sv[2 * np],     qfl, &bf[0]);
                    mma16816(sv[2 * np + 1], qfl, &bf[2]);
                }
            }

            // scale into log2 domain + causal mask
            const float scl2 = 0.18033688f;   // 0.125 * log2(e)
            const int rbase = q0 + wid * 16 + (lane >> 2);
            const bool diag = (k0b + 63) > (q0 + wid * 16);
#pragma unroll
            for (int nt = 0; nt < 8; nt++) {
#pragma unroll
                for (int c = 0; c < 4; c++) {
                    float s = sv[nt][c] * scl2;
                    if (diag) {
                        int row = rbase + ((c >> 1) << 3);
                        int col = k0b + nt * 8 + (lane & 3) * 2 + (c & 1);
                        if (col > row) s = -INFINITY;
                    }
                    sv[nt][c] = s;
                }
            }
            // online softmax (exp2 domain)
#pragma unroll
            for (int half = 0; half < 2; half++) {
                int ci = half * 2;
                float mt = -INFINITY;
#pragma unroll
                for (int nt = 0; nt < 8; nt++)
                    mt = fmaxf(mt, fmaxf(sv[nt][ci], sv[nt][ci + 1]));
                mt = fmaxf(mt, __shfl_xor_sync(0xffffffffu, mt, 1));
                mt = fmaxf(mt, __shfl_xor_sync(0xffffffffu, mt, 2));
                float mn = fmaxf(m[half], mt);
                float corr = ex2(m[half] - mn);
                m[half] = mn;
                float rs = 0.f;
#pragma unroll
                for (int nt = 0; nt < 8; nt++) {
                    float p0 = ex2(sv[nt][ci] - mn);
                    float p1 = ex2(sv[nt][ci + 1] - mn);
                    sv[nt][ci] = p0; sv[nt][ci + 1] = p1;
                    rs += p0 + p1;
                }
                rs += __shfl_xor_sync(0xffffffffu, rs, 1);
                rs += __shfl_xor_sync(0xffffffffu, rs, 2);
                lsum[half] = lsum[half] * corr + rs;
#pragma unroll
                for (int dn = 0; dn < 8; dn++) {
                    ov[dn][ci] *= corr;
                    ov[dn][ci + 1] *= corr;
                }
            }

            // O += P V : per k-step, 3 passes (ph*vh, ph*vl, pl*vh)
#pragma unroll
            for (int kt = 0; kt < 4; kt++) {
                uint32_t pfh[4], pfl[4];
                hilo2(sv[2 * kt][0],     sv[2 * kt][1],     pfh[0], pfl[0]);
                hilo2(sv[2 * kt][2],     sv[2 * kt][3],     pfh[1], pfl[1]);
                hilo2(sv[2 * kt + 1][0], sv[2 * kt + 1][1], pfh[2], pfl[2]);
                hilo2(sv[2 * kt + 1][2], sv[2 * kt + 1][3], pfh[3], pfl[3]);
#pragma unroll
                for (int dp = 0; dp < 4; dp++) {
                    uint32_t vaddr = (uint32_t)(((kt * 16 + (lane & 15)) * AS +
                                                 dp * 16 + (lane >> 4) * 8) * 2);
                    uint32_t vf[4];
                    ldm4t(sb + bo + AVHO + vaddr, vf);
                    mma16816(ov[2 * dp],     pfh, &vf[0]);
                    mma16816(ov[2 * dp + 1], pfh, &vf[2]);
                }
#pragma unroll
                for (int dp = 0; dp < 4; dp++) {
                    uint32_t vaddr = (uint32_t)(((kt * 16 + (lane & 15)) * AS +
                                                 dp * 16 + (lane >> 4) * 8) * 2);
                    uint32_t vf[4];
                    ldm4t(sb + bo + AVLO + vaddr, vf);
                    mma16816(ov[2 * dp],     pfh, &vf[0]);
                    mma16816(ov[2 * dp + 1], pfh, &vf[2]);
                }
#pragma unroll
                for (int dp = 0; dp < 4; dp++) {
                    uint32_t vaddr = (uint32_t)(((kt * 16 + (lane & 15)) * AS +
                                                 dp * 16 + (lane >> 4) * 8) * 2);
                    uint32_t vf[4];
                    ldm4t(sb + bo + AVHO + vaddr, vf);
                    mma16816(ov[2 * dp],     pfl, &vf[0]);
                    mma16816(ov[2 * dp + 1], pfl, &vf[2]);
                }
            }
        }
    }

    // epilogue: write UNNORMALIZED partial O + (m, lsum) for this half
    const int r = lane >> 2, cq = (lane & 3) * 2;
#pragma unroll
    for (int half = 0; half < 2; half++) {
        int rg = q0 + wid * 16 + r + half * 8;
        g_pml[z][h][rg][0] = m[half];       // quad-redundant, same value
        g_pml[z][h][rg][1] = lsum[half];
#pragma unroll
        for (int dn = 0; dn < 8; dn++) {
            *(float2*)&g_pO[z][h][rg][dn * 8 + cq] =
                make_float2(ov[dn][half * 2], ov[dn][half * 2 + 1]);
        }
    }
}

// ---------------------------------------------------------------------------
// Combine the two KV halves:  O = (w0*O0 + w1*O1) / (w0*l0 + w1*l1),
// w_z = 2^(m_z - max(m0, m1)).  Writes bf16 hi/lo att [T, 768].
// ---------------------------------------------------------------------------
__global__ __launch_bounds__(256) void combine_kv() {
    int idx = blockIdx.x * 256 + threadIdx.x;     // over NH*T_SEQ*32
    int h = idx / (T_SEQ * 32);
    int rem = idx - h * (T_SEQ * 32);
    int row = rem >> 5;
    int c2 = (rem & 31) * 2;
    float m0 = g_pml[0][h][row][0], l0 = g_pml[0][h][row][1];
    float m1 = g_pml[1][h][row][0], l1 = g_pml[1][h][row][1];
    float mm = fmaxf(m0, m1);
    float w0 = ex2(m0 - mm), w1 = ex2(m1 - mm);
    float inv = 1.f / (l0 * w0 + l1 * w1);
    float2 o0 = *(float2*)&g_pO[0][h][row][c2];
    float2 o1 = *(float2*)&g_pO[1][h][row][c2];
    float v0 = (o0.x * w0 + o1.x * w1) * inv;
    float v1 = (o0.y * w0 + o1.y * w1) * inv;
    uint32_t hh, ll;
    hilo2(v0, v1, hh, ll);
    size_t base = (size_t)row * C_EMB + h * HD + c2;
    *(uint32_t*)(g_ahi + base) = hh;
    *(uint32_t*)(g_alo + base) = ll;
}

// ---------------------------------------------------------------------------
extern "C" void kernel_launch(void* const* d_in, const int* in_sizes, int n_in,
                              void* d_out, int out_size) {
    (void)in_sizes; (void)n_in; (void)out_size;
    const float* x  = (const float*)d_in[0];
    const float* wq = (const float*)d_in[1];
    const float* wk = (const float*)d_in[2];
    const float* wv = (const float*)d_in[3];
    const float* wo = (const float*)d_in[4];
    float* out = (float*)d_out;

    bf16 *xhi, *xlo, *whi, *wlo, *ahi, *alo;
    cudaGetSymbolAddress((void**)&xhi, g_xhi);
    cudaGetSymbolAddress((void**)&xlo, g_xlo);
    cudaGetSymbolAddress((void**)&whi, g_whi);
    cudaGetSymbolAddress((void**)&wlo, g_wlo);
    cudaGetSymbolAddress((void**)&ahi, g_ahi);
    cudaGetSymbolAddress((void**)&alo, g_alo);
    cudaFuncSetAttribute(gemm_tc, cudaFuncAttributeMaxDynamicSharedMemorySize,
                         GEMM_SMEM);
    cudaFuncSetAttribute(attn_tc, cudaFuncAttributeMaxDynamicSharedMemorySize,
                         ATTN_SMEM);
    const size_t WSZ = (size_t)C_EMB * C_EMB;

    int ntot = NX4 + 4 * NW4;
    split_all<<<(ntot + 255) / 256, 256>>>(x, wq, wk, wv, wo);

    dim3 ggrid(T_SEQ / 128, C_EMB / 64, 3);    // fused QKV: 1152 CTAs
    gemm_tc<<<ggrid, 256, GEMM_SMEM>>>(xhi, xlo, whi, wlo, nullptr);

    dim3 agrid(T_SEQ / 128, NH, 2);            // split-KV: 768 CTAs
    attn_tc<<<agrid, 256, ATTN_SMEM>>>();

    combine_kv<<<(NH * T_SEQ * 32) / 256, 256>>>();

    dim3 ogrid(T_SEQ / 128, C_EMB / 64, 1);    // WO: 384 CTAs
    gemm_tc<<<ogrid, 256, GEMM_SMEM>>>(ahi, alo, whi + 3 * WSZ, wlo + 3 * WSZ, out);
}

// round 16
// speedup vs baseline: 1.0761x; 1.0050x over previous
#include <cuda_runtime.h>
#include <cuda_bf16.h>
#include <math.h>
#include <stdint.h>

#define T_SEQ 4096
#define C_EMB 768
#define NH    12
#define HD    64
#define NW4   147456          // (768*768)/4
#define NX4   786432          // (4096*768)/4

typedef __nv_bfloat16 bf16;
typedef __nv_bfloat162 bf162;

// ---------------------------------------------------------------------------
// Scratch (__device__ globals — allocation-guard-safe)
// ---------------------------------------------------------------------------
__device__ __align__(128) bf16 g_xhi[(size_t)T_SEQ * C_EMB];
__device__ __align__(128) bf16 g_xlo[(size_t)T_SEQ * C_EMB];
__device__ __align__(128) bf16 g_whi[4][(size_t)C_EMB * C_EMB];
__device__ __align__(128) bf16 g_wlo[4][(size_t)C_EMB * C_EMB];
__device__ __align__(128) bf16 g_qhi[(size_t)NH * T_SEQ * HD];
__device__ __align__(128) bf16 g_qlo[(size_t)NH * T_SEQ * HD];
__device__ __align__(128) bf16 g_khi[(size_t)NH * T_SEQ * HD];
__device__ __align__(128) bf16 g_klo[(size_t)NH * T_SEQ * HD];
__device__ __align__(128) bf16 g_vhi[(size_t)NH * T_SEQ * HD];
__device__ __align__(128) bf16 g_vlo[(size_t)NH * T_SEQ * HD];
__device__ __align__(128) bf16 g_ahi[(size_t)T_SEQ * C_EMB];
__device__ __align__(128) bf16 g_alo[(size_t)T_SEQ * C_EMB];
// split-KV partials: unnormalized O + (m, lsum) per row, 2 halves
__device__ __align__(128) float g_pO[2][NH][T_SEQ][HD];     // 25.2 MB
__device__ __align__(128) float g_pml[2][NH][T_SEQ][2];     // 786 KB

// ---------------------------------------------------------------------------
// Helpers (baseline PTX only — no 'a'-arch features)
// ---------------------------------------------------------------------------
__device__ __forceinline__ uint32_t smem_u32(const void* p) {
    uint32_t a;
    asm("{ .reg .u64 t; cvta.to.shared.u64 t, %1; cvt.u32.u64 %0, t; }"
        : "=r"(a) : "l"(p));
    return a;
}
__device__ __forceinline__ void ldm4(uint32_t addr, uint32_t* r) {
    asm volatile("ldmatrix.sync.aligned.m8n8.x4.shared.b16 {%0,%1,%2,%3}, [%4];"
                 : "=r"(r[0]), "=r"(r[1]), "=r"(r[2]), "=r"(r[3]) : "r"(addr));
}
__device__ __forceinline__ void ldm4t(uint32_t addr, uint32_t* r) {
    asm volatile("ldmatrix.sync.aligned.m8n8.x4.trans.shared.b16 {%0,%1,%2,%3}, [%4];"
                 : "=r"(r[0]), "=r"(r[1]), "=r"(r[2]), "=r"(r[3]) : "r"(addr));
}
__device__ __forceinline__ void mma16816(float* d, const uint32_t* a,
                                         const uint32_t* b) {
    asm volatile(
        "mma.sync.aligned.m16n8k16.row.col.f32.bf16.bf16.f32 "
        "{%0,%1,%2,%3}, {%4,%5,%6,%7}, {%8,%9}, {%0,%1,%2,%3};"
        : "+f"(d[0]), "+f"(d[1]), "+f"(d[2]), "+f"(d[3])
        : "r"(a[0]), "r"(a[1]), "r"(a[2]), "r"(a[3]), "r"(b[0]), "r"(b[1]));
}
__device__ __forceinline__ float ex2(float x) {
    float y;
    asm("ex2.approx.f32 %0, %1;" : "=f"(y) : "f"(x));
    return y;
}
__device__ __forceinline__ void hilo2(float v0, float v1, uint32_t& h, uint32_t& l) {
    bf162 hh, ll;
    hh.x = __float2bfloat16(v0); hh.y = __float2bfloat16(v1);
    ll.x = __float2bfloat16(v0 - __bfloat162float(hh.x));
    ll.y = __float2bfloat16(v1 - __bfloat162float(hh.y));
    h = *reinterpret_cast<uint32_t*>(&hh);
    l = *reinterpret_cast<uint32_t*>(&ll);
}
#define CP16(dst, src) \
    asm volatile("cp.async.cg.shared.global [%0], [%1], 16;" \
                 :: "r"(dst), "l"(src) : "memory")
#define CPCOMMIT() asm volatile("cp.async.commit_group;" ::: "memory")
#define CPWAIT0() asm volatile("cp.async.wait_group 0;" ::: "memory")

// ---------------------------------------------------------------------------
// fp32 -> bf16 (hi, lo) split: x and all 4 weights in one launch
// ---------------------------------------------------------------------------
__global__ __launch_bounds__(256) void split_all(const float* __restrict__ x,
                                                 const float* __restrict__ w0,
                                                 const float* __restrict__ w1,
                                                 const float* __restrict__ w2,
                                                 const float* __restrict__ w3) {
    int i = blockIdx.x * 256 + threadIdx.x;
    const float* src;
    uint32_t *hp, *lp;
    int j;
    if (i < NX4) {
        src = x; j = i;
        hp = (uint32_t*)g_xhi; lp = (uint32_t*)g_xlo;
    } else {
        int t = i - NX4;
        int m = t / NW4;
        if (m >= 4) return;
        j = t - m * NW4;
        src = (m == 0) ? w0 : (m == 1) ? w1 : (m == 2) ? w2 : w3;
        hp = (uint32_t*)(g_whi[m]); lp = (uint32_t*)(g_wlo[m]);
    }
    float4 v = ((const float4*)src)[j];
    uint32_t h0, l0, h1, l1;
    hilo2(v.x, v.y, h0, l0);
    hilo2(v.z, v.w, h1, l1);
    hp[j * 2 + 0] = h0; hp[j * 2 + 1] = h1;
    lp[j * 2 + 0] = l0; lp[j * 2 + 1] = l1;
}

// ---------------------------------------------------------------------------
// QKV GEMM: CTA tile 128x128, 8 warps (4m x 2n, each 32x64). k-chunk 32,
// double-buffered cp.async, single sync per stage. MMA order cycles 4
// accumulators per B-fragment pair (dep distance 4).
// stage: AH @0 AL @10240 BH @20480 BL @30720 (40960 B), row stride 40 bf16.
// z selects weight; writes bf16 hi/lo head-major.
// ---------------------------------------------------------------------------
#define QS 40
#define QAL 10240
#define QBH 20480
#define QBL 30720
#define QSTG 40960
#define QKV_SMEM 81920
#define QNST (C_EMB / 32)     // 24

__global__ __launch_bounds__(256, 2) void qkv_tc(
    const bf16* __restrict__ Ahi, const bf16* __restrict__ Alo,
    const bf16* __restrict__ BhiB, const bf16* __restrict__ BloB) {
    extern __shared__ bf16 smq[];
    const uint32_t sb = smem_u32(smq);
    const int tid = threadIdx.x, lane = tid & 31, wid = tid >> 5;
    const int wm = wid & 3, wn = wid >> 2;
    const int row0 = blockIdx.x * 128;
    const int col0 = blockIdx.y * 128;
    const int z = blockIdx.z;
    const bf16* Bhi = BhiB + (size_t)z * C_EMB * C_EMB;
    const bf16* Blo = BloB + (size_t)z * C_EMB * C_EMB;
    const int g = lane >> 3, lr = lane & 7;

    float acc[2][8][4];
#pragma unroll
    for (int i = 0; i < 2; i++)
#pragma unroll
        for (int j = 0; j < 8; j++)
#pragma unroll
            for (int c = 0; c < 4; c++) acc[i][j][c] = 0.f;

    auto pf = [&](int s, uint32_t bo) {
        int k0 = s * 32;
#pragma unroll
        for (int itr = 0; itr < 2; itr++) {
            int idx = tid + itr * 256;           // 0..511
            int r = idx >> 2, q = idx & 3;
            size_t ga = (size_t)(row0 + r) * C_EMB + k0 + q * 8;
            size_t gb = (size_t)(col0 + r) * C_EMB + k0 + q * 8;
            uint32_t so = (uint32_t)((r * QS + q * 8) * 2);
            CP16(sb + bo + so,       Ahi + ga);
            CP16(sb + bo + QAL + so, Alo + ga);
            CP16(sb + bo + QBH + so, Bhi + gb);
            CP16(sb + bo + QBL + so, Blo + gb);
        }
    };

    pf(0, 0u);
    CPCOMMIT();

    for (int s = 0; s < QNST; s++) {
        const uint32_t bo = (s & 1) ? (uint32_t)QSTG : 0u;
        CPWAIT0();
        __syncthreads();
        if (s + 1 < QNST) {
            pf(s + 1, ((s + 1) & 1) ? (uint32_t)QSTG : 0u);
            CPCOMMIT();
        }

#pragma unroll
        for (int kt = 0; kt < 2; kt++) {
            uint32_t ah[2][4], al[2][4];
#pragma unroll
            for (int mt = 0; mt < 2; mt++) {
                uint32_t aoff = (uint32_t)(((wm * 32 + mt * 16 + lr + (g & 1) * 8) * QS +
                                            kt * 16 + (g >> 1) * 8) * 2);
                ldm4(sb + bo + aoff, ah[mt]);
                ldm4(sb + bo + QAL + aoff, al[mt]);
            }
#pragma unroll
            for (int np = 0; np < 4; np++) {
                uint32_t boff = (uint32_t)(((wn * 64 + np * 16 + lr + (g >> 1) * 8) * QS +
                                            kt * 16 + (g & 1) * 8) * 2);
                uint32_t bh[4], bl[4];
                ldm4(sb + bo + QBH + boff, bh);
                ldm4(sb + bo + QBL + boff, bl);
                // term 1: ah*bh — 4 accs rotate
                mma16816(acc[0][2 * np],     ah[0], &bh[0]);
                mma16816(acc[1][2 * np],     ah[1], &bh[0]);
                mma16816(acc[0][2 * np + 1], ah[0], &bh[2]);
                mma16816(acc[1][2 * np + 1], ah[1], &bh[2]);
                // term 2: ah*bl
                mma16816(acc[0][2 * np],     ah[0], &bl[0]);
                mma16816(acc[1][2 * np],     ah[1], &bl[0]);
                mma16816(acc[0][2 * np + 1], ah[0], &bl[2]);
                mma16816(acc[1][2 * np + 1], ah[1], &bl[2]);
                // term 3: al*bh
                mma16816(acc[0][2 * np],     al[0], &bh[0]);
                mma16816(acc[1][2 * np],     al[1], &bh[0]);
                mma16816(acc[0][2 * np + 1], al[0], &bh[2]);
                mma16816(acc[1][2 * np + 1], al[1], &bh[2]);
            }
        }
    }

    const int r = lane >> 2, cq = (lane & 3) * 2;
    bf16* Dhi = (z == 0) ? g_qhi : (z == 1) ? g_khi : g_vhi;
    bf16* Dlo = (z == 0) ? g_qlo : (z == 1) ? g_klo : g_vlo;
#pragma unroll
    for (int mt = 0; mt < 2; mt++) {
#pragma unroll
        for (int nt = 0; nt < 8; nt++) {
            int grow = row0 + wm * 32 + mt * 16 + r;
            int gc = col0 + wn * 64 + nt * 8 + cq;
            uint32_t h0, l0, h1, l1;
            hilo2(acc[mt][nt][0], acc[mt][nt][1], h0, l0);
            hilo2(acc[mt][nt][2], acc[mt][nt][3], h1, l1);
            int hh = gc >> 6, d = gc & 63;
            size_t b0 = ((size_t)hh * T_SEQ + grow) * HD + d;
            size_t b1 = ((size_t)hh * T_SEQ + grow + 8) * HD + d;
            *(uint32_t*)(Dhi + b0) = h0;
            *(uint32_t*)(Dlo + b0) = l0;
            *(uint32_t*)(Dhi + b1) = h1;
            *(uint32_t*)(Dlo + b1) = l1;
        }
    }
}

// ---------------------------------------------------------------------------
// WO GEMM: CTA tile 128x64 (proven at 52 us), k-chunk 64, double-buffered,
// single sync. fp32 output.
// ---------------------------------------------------------------------------
#define GS 72
#define GAL 18432
#define GBH 36864
#define GBL 46080
#define GSTG 55296
#define GEMM_SMEM 110592
#define NSTG (C_EMB / 64)     // 12

__global__ __launch_bounds__(256, 2) void gemm_tc(
    const bf16* __restrict__ Ahi, const bf16* __restrict__ Alo,
    const bf16* __restrict__ Bhi, const bf16* __restrict__ Blo,
    float* __restrict__ outf) {
    extern __shared__ bf16 smg[];
    const uint32_t sb = smem_u32(smg);
    const int tid = threadIdx.x, lane = tid & 31, wid = tid >> 5;
    const int row0 = blockIdx.x * 128;
    const int col0 = blockIdx.y * 64;
    const int g = lane >> 3, lr = lane & 7;

    float acc[8][4];
#pragma unroll
    for (int j = 0; j < 8; j++)
#pragma unroll
        for (int c = 0; c < 4; c++) acc[j][c] = 0.f;

    auto pf = [&](int s, uint32_t bo) {
        int k0 = s * 64;
#pragma unroll
        for (int itr = 0; itr < 4; itr++) {
            int idx = tid + itr * 256;
            int r = idx >> 3, q = idx & 7;
            uint32_t so = (uint32_t)((r * GS + q * 8) * 2);
            size_t ga = (size_t)(row0 + r) * C_EMB + k0 + q * 8;
            CP16(sb + bo + so,       Ahi + ga);
            CP16(sb + bo + GAL + so, Alo + ga);
        }
#pragma unroll
        for (int itr = 0; itr < 2; itr++) {
            int idx = tid + itr * 256;
            int r = idx >> 3, q = idx & 7;
            uint32_t so = (uint32_t)((r * GS + q * 8) * 2);
            size_t gb = (size_t)(col0 + r) * C_EMB + k0 + q * 8;
            CP16(sb + bo + GBH + so, Bhi + gb);
            CP16(sb + bo + GBL + so, Blo + gb);
        }
    };

    pf(0, 0u);
    CPCOMMIT();

    for (int s = 0; s < NSTG; s++) {
        const uint32_t bo = (s & 1) ? (uint32_t)GSTG : 0u;
        CPWAIT0();
        __syncthreads();
        if (s + 1 < NSTG) {
            pf(s + 1, ((s + 1) & 1) ? (uint32_t)GSTG : 0u);
            CPCOMMIT();
        }

#pragma unroll
        for (int kt = 0; kt < 4; kt++) {
            uint32_t ah[4], al[4];
            uint32_t aoff = (uint32_t)(((wid * 16 + lr + (g & 1) * 8) * GS +
                                        kt * 16 + (g >> 1) * 8) * 2);
            ldm4(sb + bo + aoff, ah);
            ldm4(sb + bo + GAL + aoff, al);
#pragma unroll
            for (int np = 0; np < 4; np++) {
                uint32_t boff = (uint32_t)(((np * 16 + lr + (g >> 1) * 8) * GS +
                                            kt * 16 + (g & 1) * 8) * 2);
                uint32_t bh[4], bl[4];
                ldm4(sb + bo + GBH + boff, bh);
                ldm4(sb + bo + GBL + boff, bl);
                mma16816(acc[2 * np],     ah, &bh[0]);
                mma16816(acc[2 * np + 1], ah, &bh[2]);
                mma16816(acc[2 * np],     ah, &bl[0]);
                mma16816(acc[2 * np + 1], ah, &bl[2]);
                mma16816(acc[2 * np],     al, &bh[0]);
                mma16816(acc[2 * np + 1], al, &bh[2]);
            }
        }
    }

    const int r = lane >> 2, cq = (lane & 3) * 2;
    const int grow = row0 + wid * 16 + r;
#pragma unroll
    for (int nt = 0; nt < 8; nt++) {
        int d = nt * 8 + cq;
        *(float2*)(outf + (size_t)grow * C_EMB + col0 + d) =
            make_float2(acc[nt][0], acc[nt][1]);
        *(float2*)(outf + (size_t)(grow + 8) * C_EMB + col0 + d) =
            make_float2(acc[nt][2], acc[nt][3]);
    }
}

// ---------------------------------------------------------------------------
// Split-KV tensor flash attention, causal. BLOCK_M=128, BLOCK_N=64.
// Grid (32, NH, 2). Single sync per tile; 3-pass term ordering.
// stage: KH=+0 KL=+9216 VH=+18432 VL=+27648 (36864 B); Q @73728/92160.
// ---------------------------------------------------------------------------
#define AS  72
#define STG 36864
#define AVHO 18432
#define AVLO 27648
#define AQH 73728
#define AQL 92160
#define ATTN_SMEM 110592

__global__ __launch_bounds__(256, 2) void attn_tc() {
    extern __shared__ char smc[];
    const uint32_t sb = smem_u32(smc);
    const int tid = threadIdx.x, lane = tid & 31, wid = tid >> 5;
    const int g = lane >> 3, lr = lane & 7;
    const int itc = gridDim.x - 1 - blockIdx.x;   // heavy first
    const int h = blockIdx.y;
    const int z = blockIdx.z;                     // KV split half
    const int q0 = itc * 128;
    const int cnt = itc + 1;                      // tiles in this half

    const bf16* Qh = g_qhi + (size_t)h * T_SEQ * HD;
    const bf16* Ql = g_qlo + (size_t)h * T_SEQ * HD;
    const bf16* Kh = g_khi + (size_t)h * T_SEQ * HD;
    const bf16* Kl = g_klo + (size_t)h * T_SEQ * HD;
    const bf16* Vh = g_vhi + (size_t)h * T_SEQ * HD;
    const bf16* Vl = g_vlo + (size_t)h * T_SEQ * HD;

#pragma unroll
    for (int itr = 0; itr < 4; itr++) {
        int idx = tid + itr * 256;
        int r = idx >> 3, q = idx & 7;
        uint32_t so = (uint32_t)((r * AS + q * 8) * 2);
        size_t gofs = (size_t)(q0 + r) * HD + q * 8;
        CP16(sb + AQH + so, Qh + gofs);
        CP16(sb + AQL + so, Ql + gofs);
    }

    auto prefetch = [&](int jt2, uint32_t bo) {
        int k0b = jt2 * 64;
#pragma unroll
        for (int itr = 0; itr < 2; itr++) {
            int idx = tid + itr * 256;
            int r = idx >> 3, q = idx & 7;
            uint32_t so = (uint32_t)((r * AS + q * 8) * 2);
            size_t gofs = (size_t)(k0b + r) * HD + q * 8;
            CP16(sb + bo + so,          Kh + gofs);
            CP16(sb + bo + 9216 + so,   Kl + gofs);
            CP16(sb + bo + AVHO + so,   Vh + gofs);
            CP16(sb + bo + AVLO + so,   Vl + gofs);
        }
    };

    float m[2] = {-INFINITY, -INFINITY}, lsum[2] = {0.f, 0.f};
    float ov[8][4];
#pragma unroll
    for (int i = 0; i < 8; i++)
#pragma unroll
        for (int c = 0; c < 4; c++) ov[i][c] = 0.f;

    prefetch(z, 0u);
    CPCOMMIT();

    const uint32_t qoff_base = (uint32_t)(((wid * 16 + lr + (g & 1) * 8) * AS +
                                           (g >> 1) * 8) * 2);

    for (int lt = 0; lt < cnt; lt++) {
        const int jt = z + 2 * lt;
        const uint32_t bo = (lt & 1) ? (uint32_t)STG : 0u;
        CPWAIT0();
        __syncthreads();
        if (lt + 1 < cnt) {
            prefetch(z + 2 * (lt + 1), ((lt + 1) & 1) ? (uint32_t)STG : 0u);
            CPCOMMIT();
        }

        const int k0b = jt * 64;
        const bool skip = (wid * 16 + 15) < (k0b - q0);
        if (!skip) {
            float sv[8][4];
#pragma unroll
            for (int i = 0; i < 8; i++)
#pragma unroll
                for (int c = 0; c < 4; c++) sv[i][c] = 0.f;
#pragma unroll
            for (int kt = 0; kt < 4; kt++) {
                uint32_t qfh[4], qfl[4];
                uint32_t qa = qoff_base + (uint32_t)(kt * 32);
                ldm4(sb + AQH + qa, qfh);
                ldm4(sb + AQL + qa, qfl);
#pragma unroll
                for (int np = 0; np < 4; np++) {
                    uint32_t boff = (uint32_t)(((np * 16 + lr + (g >> 1) * 8) * AS +
                                                kt * 16 + (g & 1) * 8) * 2);
                    uint32_t bh[4], bl[4];
                    ldm4(sb + bo + boff, bh);
                    ldm4(sb + bo + 9216 + boff, bl);
                    mma16816(sv[2 * np],     qfh, &bh[0]);
                    mma16816(sv[2 * np + 1], qfh, &bh[2]);
                    mma16816(sv[2 * np],     qfh, &bl[0]);
                    mma16816(sv[2 * np + 1], qfh, &bl[2]);
                    mma16816(sv[2 * np],     qfl, &bh[0]);
                    mma16816(sv[2 * np + 1], qfl, &bh[2]);
                }
            }

            const float scl2 = 0.18033688f;   // 0.125 * log2(e)
            const int rbase = q0 + wid * 16 + (lane >> 2);
            const bool diag = (k0b + 63) > (q0 + wid * 16);
#pragma unroll
            for (int nt = 0; nt < 8; nt++) {
#pragma unroll
                for (int c = 0; c < 4; c++) {
                    float s = sv[nt][c] * scl2;
                    if (diag) {
                        int row = rbase + ((c >> 1) << 3);
                        int col = k0b + nt * 8 + (lane & 3) * 2 + (c & 1);
                        if (col > row) s = -INFINITY;
                    }
                    sv[nt][c] = s;
                }
            }
#pragma unroll
            for (int half = 0; half < 2; half++) {
                int ci = half * 2;
                float mt = -INFINITY;
#pragma unroll
                for (int nt = 0; nt < 8; nt++)
                    mt = fmaxf(mt, fmaxf(sv[nt][ci], sv[nt][ci + 1]));
                mt = fmaxf(mt, __shfl_xor_sync(0xffffffffu, mt, 1));
                mt = fmaxf(mt, __shfl_xor_sync(0xffffffffu, mt, 2));
                float mn = fmaxf(m[half], mt);
                float corr = ex2(m[half] - mn);
                m[half] = mn;
                float rs = 0.f;
#pragma unroll
                for (int nt = 0; nt < 8; nt++) {
                    float p0 = ex2(sv[nt][ci] - mn);
                    float p1 = ex2(sv[nt][ci + 1] - mn);
                    sv[nt][ci] = p0; sv[nt][ci + 1] = p1;
                    rs += p0 + p1;
                }
                rs += __shfl_xor_sync(0xffffffffu, rs, 1);
                rs += __shfl_xor_sync(0xffffffffu, rs, 2);
                lsum[half] = lsum[half] * corr + rs;
#pragma unroll
                for (int dn = 0; dn < 8; dn++) {
                    ov[dn][ci] *= corr;
                    ov[dn][ci + 1] *= corr;
                }
            }

#pragma unroll
            for (int kt = 0; kt < 4; kt++) {
                uint32_t pfh[4], pfl[4];
                hilo2(sv[2 * kt][0],     sv[2 * kt][1],     pfh[0], pfl[0]);
                hilo2(sv[2 * kt][2],     sv[2 * kt][3],     pfh[1], pfl[1]);
                hilo2(sv[2 * kt + 1][0], sv[2 * kt + 1][1], pfh[2], pfl[2]);
                hilo2(sv[2 * kt + 1][2], sv[2 * kt + 1][3], pfh[3], pfl[3]);
#pragma unroll
                for (int dp = 0; dp < 4; dp++) {
                    uint32_t vaddr = (uint32_t)(((kt * 16 + (lane & 15)) * AS +
                                                 dp * 16 + (lane >> 4) * 8) * 2);
                    uint32_t vfh[4], vfl[4];
                    ldm4t(sb + bo + AVHO + vaddr, vfh);
                    ldm4t(sb + bo + AVLO + vaddr, vfl);
                    mma16816(ov[2 * dp],     pfh, &vfh[0]);
                    mma16816(ov[2 * dp + 1], pfh, &vfh[2]);
                    mma16816(ov[2 * dp],     pfh, &vfl[0]);
                    mma16816(ov[2 * dp + 1], pfh, &vfl[2]);
                    mma16816(ov[2 * dp],     pfl, &vfh[0]);
                    mma16816(ov[2 * dp + 1], pfl, &vfh[2]);
                }
            }
        }
    }

    const int r = lane >> 2, cq = (lane & 3) * 2;
#pragma unroll
    for (int half = 0; half < 2; half++) {
        int rg = q0 + wid * 16 + r + half * 8;
        g_pml[z][h][rg][0] = m[half];
        g_pml[z][h][rg][1] = lsum[half];
#pragma unroll
        for (int dn = 0; dn < 8; dn++) {
            *(float2*)&g_pO[z][h][rg][dn * 8 + cq] =
                make_float2(ov[dn][half * 2], ov[dn][half * 2 + 1]);
        }
    }
}

// ---------------------------------------------------------------------------
// Combine the two KV halves.
// ---------------------------------------------------------------------------
__global__ __launch_bounds__(256) void combine_kv() {
    int idx = blockIdx.x * 256 + threadIdx.x;
    int h = idx / (T_SEQ * 32);
    int rem = idx - h * (T_SEQ * 32);
    int row = rem >> 5;
    int c2 = (rem & 31) * 2;
    float m0 = g_pml[0][h][row][0], l0 = g_pml[0][h][row][1];
    float m1 = g_pml[1][h][row][0], l1 = g_pml[1][h][row][1];
    float mm = fmaxf(m0, m1);
    float w0 = ex2(m0 - mm), w1 = ex2(m1 - mm);
    float inv = 1.f / (l0 * w0 + l1 * w1);
    float2 o0 = *(float2*)&g_pO[0][h][row][c2];
    float2 o1 = *(float2*)&g_pO[1][h][row][c2];
    float v0 = (o0.x * w0 + o1.x * w1) * inv;
    float v1 = (o0.y * w0 + o1.y * w1) * inv;
    uint32_t hh, ll;
    hilo2(v0, v1, hh, ll);
    size_t base = (size_t)row * C_EMB + h * HD + c2;
    *(uint32_t*)(g_ahi + base) = hh;
    *(uint32_t*)(g_alo + base) = ll;
}

// ---------------------------------------------------------------------------
extern "C" void kernel_launch(void* const* d_in, const int* in_sizes, int n_in,
                              void* d_out, int out_size) {
    (void)in_sizes; (void)n_in; (void)out_size;
    const float* x  = (const float*)d_in[0];
    const float* wq = (const float*)d_in[1];
    const float* wk = (const float*)d_in[2];
    const float* wv = (const float*)d_in[3];
    const float* wo = (const float*)d_in[4];
    float* out = (float*)d_out;

    bf16 *xhi, *xlo, *whi, *wlo, *ahi, *alo;
    cudaGetSymbolAddress((void**)&xhi, g_xhi);
    cudaGetSymbolAddress((void**)&xlo, g_xlo);
    cudaGetSymbolAddress((void**)&whi, g_whi);
    cudaGetSymbolAddress((void**)&wlo, g_wlo);
    cudaGetSymbolAddress((void**)&ahi, g_ahi);
    cudaGetSymbolAddress((void**)&alo, g_alo);
    cudaFuncSetAttribute(qkv_tc, cudaFuncAttributeMaxDynamicSharedMemorySize,
                         QKV_SMEM);
    cudaFuncSetAttribute(gemm_tc, cudaFuncAttributeMaxDynamicSharedMemorySize,
                         GEMM_SMEM);
    cudaFuncSetAttribute(attn_tc, cudaFuncAttributeMaxDynamicSharedMemorySize,
                         ATTN_SMEM);
    const size_t WSZ = (size_t)C_EMB * C_EMB;

    int ntot = NX4 + 4 * NW4;
    split_all<<<(ntot + 255) / 256, 256>>>(x, wq, wk, wv, wo);

    dim3 qgrid(T_SEQ / 128, C_EMB / 128, 3);   // QKV: 576 CTAs, 128x128 tiles
    qkv_tc<<<qgrid, 256, QKV_SMEM>>>(xhi, xlo, whi, wlo);

    dim3 agrid(T_SEQ / 128, NH, 2);            // split-KV: 768 CTAs
    attn_tc<<<agrid, 256, ATTN_SMEM>>>();

    combine_kv<<<(NH * T_SEQ * 32) / 256, 256>>>();

    dim3 ogrid(T_SEQ / 128, C_EMB / 64);       // WO: 384 CTAs, 128x64 tiles
    gemm_tc<<<ogrid, 256, GEMM_SMEM>>>(ahi, alo, whi + 3 * WSZ, wlo + 3 * WSZ, out);
}